// round 14
// baseline (speedup 1.0000x reference)
#include <cuda_runtime.h>
#include <math.h>
#include <stdint.h>

#define R    16384      // B*S rows
#define D    256
#define F    256
#define NB   16
#define TMAX 8192
#define KKC  768        // 3 * 256 im2col K

typedef unsigned long long u64;

// ---------------- scratch (static device allocations only) ----------------
__device__ float g_xp[R * D];
__device__ float g_xn[R * D];
__device__ float g_h1[R * F];
__device__ float g_h2[R * F];
__device__ float g_h3[R * F];
__device__ float g_h4[R * F];
__device__ float g_h5[R * F];
__device__ float g_h6[R * F];
__device__ float g_wt[6 * KKC * F];
__device__ float g_nxn[R];
__device__ float g_nxp[R];
__device__ unsigned g_red[3];
__device__ int   g_dint[R];
__device__ int   g_cumc[R];

// ---------------- host-side stream/event resources (created pre-run) -------
struct SideStream {
    cudaStream_t s1;
    cudaEvent_t ev0, evF, evJ, evW, evL;
    SideStream() {
        cudaStreamCreateWithFlags(&s1, cudaStreamNonBlocking);
        cudaEventCreateWithFlags(&ev0, cudaEventDisableTiming);
        cudaEventCreateWithFlags(&evF, cudaEventDisableTiming);
        cudaEventCreateWithFlags(&evJ, cudaEventDisableTiming);
        cudaEventCreateWithFlags(&evW, cudaEventDisableTiming);
        cudaEventCreateWithFlags(&evL, cudaEventDisableTiming);
    }
};
static SideStream g_ss;

// =================== portable PTX helpers ==================================
__device__ __forceinline__ uint32_t smem_u32(const void* p) {
    uint32_t a;
    asm("{ .reg .u64 t; cvta.to.shared.u64 t, %1; cvt.u32.u64 %0, t; }" : "=r"(a) : "l"(p));
    return a;
}
__device__ __forceinline__ void cp_async16(uint32_t dst, const void* src, uint32_t srcsize) {
    asm volatile("cp.async.cg.shared.global [%0], [%1], 16, %2;"
                 :: "r"(dst), "l"(src), "r"(srcsize) : "memory");
}
#define CP_COMMIT() asm volatile("cp.async.commit_group;" ::: "memory")
#define CP_WAIT1()  asm volatile("cp.async.wait_group 1;" ::: "memory")
#define CP_WAIT0()  asm volatile("cp.async.wait_group 0;" ::: "memory")
__device__ __forceinline__ uint32_t lds32(uint32_t addr) {
    uint32_t v;
    asm volatile("ld.shared.b32 %0, [%1];" : "=r"(v) : "r"(addr));
    return v;
}
__device__ __forceinline__ void mma_tf32(float* c, const uint32_t* a, const uint32_t* b) {
    asm volatile("mma.sync.aligned.m16n8k8.row.col.f32.tf32.tf32.f32 "
                 "{%0,%1,%2,%3}, {%4,%5,%6,%7}, {%8,%9}, {%0,%1,%2,%3};"
                 : "+f"(c[0]), "+f"(c[1]), "+f"(c[2]), "+f"(c[3])
                 : "r"(a[0]), "r"(a[1]), "r"(a[2]), "r"(a[3]), "r"(b[0]), "r"(b[1]));
}
// ---- packed fp32x2 FMA (harmless if lowered to 2x FFMA) -------------------
__device__ __forceinline__ u64 pk2(float x) {
    u64 r; uint32_t xi = __float_as_uint(x);
    asm("mov.b64 %0, {%1, %1};" : "=l"(r) : "r"(xi));
    return r;
}
__device__ __forceinline__ void fma2(u64& acc, u64 a, u64 b) {
    asm("fma.rn.f32x2 %0, %1, %2, %0;" : "+l"(acc) : "l"(a), "l"(b));
}
__device__ __forceinline__ float2 up2(u64 v) {
    float2 f; uint32_t lo, hi;
    asm("mov.b64 {%0, %1}, %2;" : "=r"(lo), "=r"(hi) : "l"(v));
    f.x = __uint_as_float(lo); f.y = __uint_as_float(hi);
    return f;
}

// ---------------- init global reduction cells ------------------------------
__global__ void init_red(unsigned* red) {
    if (threadIdx.x == 0) { red[0] = 0u; red[1] = 0x7F800000u; red[2] = 0u; }
}

// ---------------- fused weight transpose -----------------------------------
__global__ void transpose_all(const float* __restrict__ dp1, const float* __restrict__ dp2,
                              const float* __restrict__ pp1, const float* __restrict__ pp2,
                              const float* __restrict__ ep1, const float* __restrict__ ep2,
                              float* __restrict__ wt)
{
    int y = blockIdx.y;
    const float* src = (y == 0) ? dp1 : (y == 1) ? dp2 : (y == 2) ? pp1 : (y == 3) ? pp2 : (y == 4) ? ep1 : ep2;
    float* dst = wt + y * (KKC * F);
    int idx = blockIdx.x * 256 + threadIdx.x;
    if (idx >= KKC * F) return;
    if (y < 2) {
        int f = idx & 255, kc = idx >> 8;
        int k = kc >> 8, c = kc & 255;
        dst[idx] = src[(f * 256 + c) * 3 + k];
    } else {
        int f = idx / KKC, kk = idx - f * KKC;
        int k = kk >> 8, c = kk & 255;
        dst[idx] = src[(f * 256 + c) * 3 + k];
    }
}

// ---------------- note-projection GEMM (fp32, exact) -----------------------
__global__ __launch_bounds__(256) void gemm_np(
    const float* __restrict__ A, const float* __restrict__ W,
    const float* __restrict__ bias, const float* __restrict__ Xadd,
    float* __restrict__ C)
{
    __shared__ float As[8][128];
    __shared__ float Bs[8][128];
    const int bm = blockIdx.x * 128, bn = blockIdx.y * 128;
    const int tid  = threadIdx.x;
    const int arow = tid >> 1,  acol = (tid & 1) << 2;
    const int brow = tid >> 5,  bcol = (tid & 31) << 2;
    const int ty = (tid >> 4) << 3, tx = (tid & 15) << 3;
    u64 acc2[8][4] = {};
    for (int k0 = 0; k0 < 256; k0 += 8) {
        float4 av = *reinterpret_cast<const float4*>(&A[(bm + arow) * 256 + k0 + acol]);
        float4 bv = *reinterpret_cast<const float4*>(&W[(k0 + brow) * 256 + bn + bcol]);
        __syncthreads();
        As[acol + 0][arow] = av.x; As[acol + 1][arow] = av.y;
        As[acol + 2][arow] = av.z; As[acol + 3][arow] = av.w;
        *reinterpret_cast<float4*>(&Bs[brow][bcol]) = bv;
        __syncthreads();
#pragma unroll
        for (int k = 0; k < 8; k++) {
            float a[8];
            *(float4*)&a[0] = *(const float4*)&As[k][ty];
            *(float4*)&a[4] = *(const float4*)&As[k][ty + 4];
            u64 ap[8];
#pragma unroll
            for (int i = 0; i < 8; i++) ap[i] = pk2(a[i]);
            const u64* b64 = reinterpret_cast<const u64*>(&Bs[k][tx]);
            u64 bp[4];
#pragma unroll
            for (int j = 0; j < 4; j++) bp[j] = b64[j];
#pragma unroll
            for (int i = 0; i < 8; i++)
#pragma unroll
                for (int j = 0; j < 4; j++) fma2(acc2[i][j], ap[i], bp[j]);
        }
    }
#pragma unroll
    for (int i = 0; i < 8; i++) {
        const int mo = (bm + ty + i) * 256 + bn + tx;
#pragma unroll
        for (int j = 0; j < 4; j += 2) {
            float2 p0 = up2(acc2[i][j]), p1 = up2(acc2[i][j + 1]);
            float4 xv = *reinterpret_cast<const float4*>(&Xadd[mo + 2 * j]);
            float4 o;
            o.x = p0.x + xv.x + bias[bn + tx + 2 * j + 0];
            o.y = p0.y + xv.y + bias[bn + tx + 2 * j + 1];
            o.z = p1.x + xv.z + bias[bn + tx + 2 * j + 2];
            o.w = p1.y + xv.w + bias[bn + tx + 2 * j + 3];
            *reinterpret_cast<float4*>(&C[mo + 2 * j]) = o;
        }
    }
}

// ---------------- conv1d GEMM fp32 (duration path — exact), 128x128 tile ---
// 2-stage smem double buffer, ONE __syncthreads per BK=8 chunk (96 chunks).
__global__ __launch_bounds__(256) void conv_gemm(
    const float* __restrict__ A, const float* __restrict__ Wt,
    const float* __restrict__ bias, float* __restrict__ C)
{
    __shared__ float As[2][8][128];
    __shared__ float Bs[2][8][128];
    const int bm = blockIdx.x * 128, bn = blockIdx.y * 128;
    const int tid  = threadIdx.x;
    const int arow = tid >> 1,  acol = (tid & 1) << 2;
    const int brow = tid >> 5,  bcol = (tid & 31) << 2;
    const int ty = (tid >> 4) << 3, tx = (tid & 15) << 3;
    const int m = bm + arow;
    const int bb = m >> 10, s = m & 1023;
    const float* Abase = A + (bb << 10) * D;
    const int NCH = KKC / 8;               // 96

    u64 acc2[8][4] = {};
    float4 av, bv;

    auto loadg = [&](int ch, float4& a4, float4& b4) {
        const int k0 = ch * 8;
        const int tap = k0 >> 8;
        const int sr  = s + tap - 1;
        const int c0  = (k0 & 255) + acol;
        a4 = make_float4(0.f, 0.f, 0.f, 0.f);
        if ((unsigned)sr < 1024u)
            a4 = *reinterpret_cast<const float4*>(Abase + sr * D + c0);
        b4 = *reinterpret_cast<const float4*>(&Wt[(k0 + brow) * F + bn + bcol]);
    };
    auto store_s = [&](int st, const float4& a4, const float4& b4) {
        As[st][acol + 0][arow] = a4.x; As[st][acol + 1][arow] = a4.y;
        As[st][acol + 2][arow] = a4.z; As[st][acol + 3][arow] = a4.w;
        *reinterpret_cast<float4*>(&Bs[st][brow][bcol]) = b4;
    };

    // prologue: chunk 0 to stage 0; prefetch chunk 1 regs
    loadg(0, av, bv);
    store_s(0, av, bv);
    loadg(1, av, bv);

    for (int ch = 0; ch < NCH; ch++) {
        __syncthreads();   // stage[ch&1] stores visible; stage[(ch+1)&1] reads (chunk ch-1) done
        if (ch + 1 < NCH)
            store_s((ch + 1) & 1, av, bv);
        if (ch + 2 < NCH)
            loadg(ch + 2, av, bv);
        const int st = ch & 1;
#pragma unroll
        for (int k = 0; k < 8; k++) {
            float a[8];
            *(float4*)&a[0] = *(const float4*)&As[st][k][ty];
            *(float4*)&a[4] = *(const float4*)&As[st][k][ty + 4];
            u64 ap[8];
#pragma unroll
            for (int i = 0; i < 8; i++) ap[i] = pk2(a[i]);
            const u64* b64 = reinterpret_cast<const u64*>(&Bs[st][k][tx]);
            u64 bp[4];
#pragma unroll
            for (int j = 0; j < 4; j++) bp[j] = b64[j];
#pragma unroll
            for (int i = 0; i < 8; i++)
#pragma unroll
                for (int j = 0; j < 4; j++) fma2(acc2[i][j], ap[i], bp[j]);
        }
    }
#pragma unroll
    for (int i = 0; i < 8; i++) {
        const int mo = (bm + ty + i) * F + bn + tx;
#pragma unroll
        for (int j = 0; j < 4; j += 2) {
            float2 p0 = up2(acc2[i][j]), p1 = up2(acc2[i][j + 1]);
            float4 o;
            o.x = fmaxf(p0.x + bias[bn + tx + 2 * j + 0], 0.f);
            o.y = fmaxf(p0.y + bias[bn + tx + 2 * j + 1], 0.f);
            o.z = fmaxf(p1.x + bias[bn + tx + 2 * j + 2], 0.f);
            o.w = fmaxf(p1.y + bias[bn + tx + 2 * j + 3], 0.f);
            *reinterpret_cast<float4*>(&C[mo + 2 * j]) = o;
        }
    }
}

// ---------------- conv1d GEMM via mma.sync tf32 (pitch/energy) -------------
// R10-proven config: 128 threads, 4 warps (2x2) at 64x64, BK=32 double buffer.
#define CCH      24
#define ASTRIDE  36
#define ATILE_B  (128 * ASTRIDE * 4)
#define STG_B    (2 * ATILE_B)
#define CM_SMEM  (2 * STG_B)               // 73728

__global__ __launch_bounds__(128) void conv_mma(
    const float* __restrict__ in0, const float* __restrict__ w0,
    const float* __restrict__ b0p, float* __restrict__ out0,
    const float* __restrict__ in1, const float* __restrict__ w1,
    const float* __restrict__ b1p, float* __restrict__ out1)
{
    extern __shared__ float smf[];
    const float* in  = (blockIdx.z == 0) ? in0 : in1;
    const float* wB  = (blockIdx.z == 0) ? w0  : w1;
    const float* bia = (blockIdx.z == 0) ? b0p : b1p;
    float* out       = (blockIdx.z == 0) ? out0 : out1;

    const int tid = threadIdx.x, lane = tid & 31, wid = tid >> 5;
    const int wm = wid >> 1, wn = wid & 1;
    const int g = lane >> 2, t = lane & 3;

    const int bm = blockIdx.x * 128, bn = blockIdx.y * 128;
    const int bb = bm >> 10, s0 = bm & 1023;
    const float* Abase = in + (bb << 10) * D;

    const uint32_t sbase = smem_u32(smf);
    float acc[4][8][4] = {};

    auto fill = [&](int ch, int st) {
        const int tap = ch >> 3;
        const int c0  = (ch & 7) * 32;
        const uint32_t aS = sbase + st * STG_B;
        const uint32_t bS = aS + ATILE_B;
#pragma unroll
        for (int i = 0; i < 8; i++) {
            int idx = i * 128 + tid;
            int r = idx >> 3, j = idx & 7;
            int sr = s0 + r + tap - 1;
            uint32_t ok = ((unsigned)sr < 1024u) ? 16u : 0u;
            const float* gp = Abase + (ok ? sr : 0) * D + c0 + j * 4;
            cp_async16(aS + (uint32_t)(r * ASTRIDE + j * 4) * 4, gp, ok);
        }
#pragma unroll
        for (int i = 0; i < 8; i++) {
            int idx = i * 128 + tid;
            int r = idx >> 3, j = idx & 7;
            const float* gp = wB + (bn + r) * KKC + tap * 256 + c0 + j * 4;
            cp_async16(bS + (uint32_t)(r * ASTRIDE + j * 4) * 4, gp, 16u);
        }
    };

    fill(0, 0);
    CP_COMMIT();

    for (int ch = 0; ch < CCH; ch++) {
        __syncthreads();
        if (ch + 1 < CCH) {
            fill(ch + 1, (ch + 1) & 1);
            CP_COMMIT();
            CP_WAIT1();
        } else {
            CP_WAIT0();
        }
        __syncthreads();

        const uint32_t aS = sbase + (ch & 1) * STG_B;
        const uint32_t bS = aS + ATILE_B;
#pragma unroll
        for (int ks = 0; ks < 4; ks++) {
            const int kb = ks * 8;
            uint32_t afr[4][4], bfr[8][2];
#pragma unroll
            for (int mt = 0; mt < 4; mt++) {
                uint32_t ab = aS + (uint32_t)((wm * 64 + mt * 16 + g) * ASTRIDE + kb + t) * 4;
                afr[mt][0] = lds32(ab);
                afr[mt][1] = lds32(ab + 8 * ASTRIDE * 4);
                afr[mt][2] = lds32(ab + 16);
                afr[mt][3] = lds32(ab + 8 * ASTRIDE * 4 + 16);
            }
#pragma unroll
            for (int nt = 0; nt < 8; nt++) {
                uint32_t bb2 = bS + (uint32_t)((wn * 64 + nt * 8 + g) * ASTRIDE + kb + t) * 4;
                bfr[nt][0] = lds32(bb2);
                bfr[nt][1] = lds32(bb2 + 16);
            }
#pragma unroll
            for (int mt = 0; mt < 4; mt++)
#pragma unroll
                for (int nt = 0; nt < 8; nt++)
                    mma_tf32(acc[mt][nt], afr[mt], bfr[nt]);
        }
    }

#pragma unroll
    for (int nt = 0; nt < 8; nt++) {
        const int col = bn + wn * 64 + nt * 8 + 2 * t;
        const float bv0 = bia[col], bv1 = bia[col + 1];
#pragma unroll
        for (int mt = 0; mt < 4; mt++) {
            const int row0 = bm + wm * 64 + mt * 16 + g;
            float2 v0, v1;
            v0.x = fmaxf(acc[mt][nt][0] + bv0, 0.f);
            v0.y = fmaxf(acc[mt][nt][1] + bv1, 0.f);
            v1.x = fmaxf(acc[mt][nt][2] + bv0, 0.f);
            v1.y = fmaxf(acc[mt][nt][3] + bv1, 0.f);
            *reinterpret_cast<float2*>(out + row0 * F + col) = v0;
            *reinterpret_cast<float2*>(out + (row0 + 8) * F + col) = v1;
        }
    }
}

// ---------------- layernorm + row norms + fused global reductions ----------
__global__ void ln_norm_k(const float* __restrict__ xp, const float* __restrict__ g,
                          const float* __restrict__ bta, float* __restrict__ xn,
                          float* __restrict__ nxn, float* __restrict__ nxp,
                          unsigned* __restrict__ red)
{
    int row  = blockIdx.x * 8 + (threadIdx.x >> 5);
    int lane = threadIdx.x & 31;
    const float* xr = xp + row * D;
    float v[8], s = 0.f;
#pragma unroll
    for (int i = 0; i < 8; i++) { v[i] = xr[lane + 32 * i]; s += v[i]; }
#pragma unroll
    for (int o = 16; o > 0; o >>= 1) s += __shfl_xor_sync(0xffffffffu, s, o);
    float mean = s * (1.f / 256.f);
    float sq = 0.f, sp = 0.f;
#pragma unroll
    for (int i = 0; i < 8; i++) { float d = v[i] - mean; sq += d * d; sp += v[i] * v[i]; }
#pragma unroll
    for (int o = 16; o > 0; o >>= 1) {
        sq += __shfl_xor_sync(0xffffffffu, sq, o);
        sp += __shfl_xor_sync(0xffffffffu, sp, o);
    }
    float r = 1.0f / sqrtf(sq * (1.f / 256.f) + 1e-5f);
    float n2 = 0.f;
#pragma unroll
    for (int i = 0; i < 8; i++) {
        float y = g[lane + 32 * i] * (v[i] - mean) * r + bta[lane + 32 * i];
        xn[row * D + lane + 32 * i] = y;
        n2 += y * y;
    }
#pragma unroll
    for (int o = 16; o > 0; o >>= 1) n2 += __shfl_xor_sync(0xffffffffu, n2, o);
    __shared__ float rn[8], rp[8];
    float vn = sqrtf(n2), vp = sqrtf(sp);
    if (lane == 0) {
        nxn[row] = vn; nxp[row] = vp;
        rn[threadIdx.x >> 5] = vn; rp[threadIdx.x >> 5] = vp;
    }
    __syncthreads();
    if (threadIdx.x == 0) {
        float m1 = rn[0], mn2 = rp[0], m2 = rp[0];
#pragma unroll
        for (int i = 1; i < 8; i++) {
            m1 = fmaxf(m1, rn[i]);
            mn2 = fminf(mn2, rp[i]); m2 = fmaxf(m2, rp[i]);
        }
        atomicMax(&red[0], __float_as_uint(m1));
        atomicMin(&red[1], __float_as_uint(mn2));
        atomicMax(&red[2], __float_as_uint(m2));
    }
}

// ---------------- heads ----------------------------------------------------
__global__ void dp_final(const float* __restrict__ h2, const float* __restrict__ wl,
                         const float* __restrict__ blp, const float* __restrict__ nxn,
                         const unsigned* __restrict__ red, float* __restrict__ o_ld,
                         float* __restrict__ o_du, int* __restrict__ dint)
{
    int row  = blockIdx.x * 8 + (threadIdx.x >> 5);
    int lane = threadIdx.x & 31;
    const float* hr = h2 + row * F;
    float dot = 0.f;
#pragma unroll
    for (int i = 0; i < 8; i++) dot += hr[lane + 32 * i] * wl[lane + 32 * i];
#pragma unroll
    for (int o = 16; o > 0; o >>= 1) dot += __shfl_xor_sync(0xffffffffu, dot, o);
    if (lane == 0) {
        float base = dot + blp[0];
        float es = 0.8f + 0.4f * (nxn[row] / __uint_as_float(red[0]));
        int s = row & 1023;
        float ps = 1.0f + 0.1f * ((float)s / 1024.0f);
        float ld = (base * es) * ps;
        o_ld[row] = ld;
        float dur = expf(ld);
        o_du[row] = dur;
        dint[row] = (int)rintf(dur);
    }
}

__global__ void pp_final(const float* __restrict__ h2, const float* __restrict__ wl,
                         const float* __restrict__ blp, const float* __restrict__ nxp,
                         const unsigned* __restrict__ red, float* __restrict__ o)
{
    int row  = blockIdx.x * 8 + (threadIdx.x >> 5);
    int lane = threadIdx.x & 31;
    const float* hr = h2 + row * F;
    float d0 = 0.f, d1 = 0.f, d2 = 0.f;
#pragma unroll
    for (int i = 0; i < 8; i++) {
        float h = hr[lane + 32 * i];
        const float* w = wl + (lane + 32 * i) * 3;
        d0 += h * w[0]; d1 += h * w[1]; d2 += h * w[2];
    }
#pragma unroll
    for (int o2 = 16; o2 > 0; o2 >>= 1) {
        d0 += __shfl_xor_sync(0xffffffffu, d0, o2);
        d1 += __shfl_xor_sync(0xffffffffu, d1, o2);
        d2 += __shfl_xor_sync(0xffffffffu, d2, o2);
    }
    if (lane == 0) {
        float p0 = d0 + blp[0], p1 = d1 + blp[1], p2 = d2 + blp[2];
        float mn = __uint_as_float(red[1]), mx = __uint_as_float(red[2]);
        float en = (nxp[row] - mn) / (mx - mn + 1e-8f);
        float f0s = 100.f + 400.f * en;
        float f0b = expf(p0) * f0s / 220.f;
        o[row * 3 + 0] = logf(f0b + 1e-8f);
        o[row * 3 + 1] = p1;
        o[row * 3 + 2] = p2;
    }
}

__global__ void ep_final(const float* __restrict__ h2, const float* __restrict__ wl,
                         const float* __restrict__ blp, float* __restrict__ o)
{
    int row  = blockIdx.x * 8 + (threadIdx.x >> 5);
    int lane = threadIdx.x & 31;
    const float* hr = h2 + row * F;
    float dot = 0.f;
#pragma unroll
    for (int i = 0; i < 8; i++) dot += hr[lane + 32 * i] * wl[lane + 32 * i];
#pragma unroll
    for (int o2 = 16; o2 > 0; o2 >>= 1) dot += __shfl_xor_sync(0xffffffffu, dot, o2);
    if (lane == 0) o[row] = dot + blp[0];
}

// ---------------- per-batch inclusive scan + clip (warp scan) --------------
__global__ void cumsum_k(const int* __restrict__ dint, int* __restrict__ cumc) {
    int b = blockIdx.x, t = threadIdx.x;
    int lane = t & 31, w = t >> 5;
    int s = dint[b * 1024 + t];
#pragma unroll
    for (int o = 1; o < 32; o <<= 1) {
        int u = __shfl_up_sync(0xffffffffu, s, o);
        if (lane >= o) s += u;
    }
    __shared__ int ws[32];
    if (lane == 31) ws[w] = s;
    __syncthreads();
    if (w == 0) {
        int x = ws[lane];
#pragma unroll
        for (int o = 1; o < 32; o <<= 1) {
            int u = __shfl_up_sync(0xffffffffu, x, o);
            if (lane >= o) x += u;
        }
        ws[lane] = x;
    }
    __syncthreads();
    int base = (w > 0) ? ws[w - 1] : 0;
    cumc[b * 1024 + t] = min(s + base, TMAX);
}

// ---------------- length regulation ----------------------------------------
__global__ __launch_bounds__(256) void expand_k(
    const float* __restrict__ xp, const int* __restrict__ cumc,
    float* __restrict__ o_exp, float* __restrict__ o_msk)
{
    __shared__ int cs[1024];
    __shared__ int idxs[128];
    int b  = blockIdx.y;
    int t0 = blockIdx.x * 128;
    int tid = threadIdx.x;
    for (int i = tid; i < 1024; i += 256) cs[i] = cumc[b * 1024 + i];
    __syncthreads();
    int cend = cs[1023];
    if (tid < 128) {
        int t = t0 + tid;
        int lo = 0, hi = 1024;
        while (lo < hi) { int mid = (lo + hi) >> 1; if (cs[mid] <= t) lo = mid + 1; else hi = mid; }
        bool mask = (t >= cend);
        idxs[tid] = mask ? -1 : min(lo, 1023);
        o_msk[b * TMAX + t] = mask ? 1.0f : 0.0f;
    }
    __syncthreads();
    const float* xb = xp + (b << 10) * D;
    float* ob = o_exp + ((long long)b * TMAX + t0) * D;
    for (int i = tid; i < 128 * 64; i += 256) {
        int fr = i >> 6, c4 = (i & 63) << 2;
        int id = idxs[fr];
        float4 v = make_float4(0.f, 0.f, 0.f, 0.f);
        if (id >= 0) v = *reinterpret_cast<const float4*>(xb + id * D + c4);
        *reinterpret_cast<float4*>(ob + (long long)fr * D + c4) = v;
    }
}

// ---------------- host orchestration ---------------------------------------
extern "C" void kernel_launch(void* const* d_in, const int* in_sizes, int n_in,
                              void* d_out, int out_size)
{
    const float* x     = (const float*)d_in[0];
    const float* nph   = (const float*)d_in[2];
    const float* ln_g  = (const float*)d_in[3];
    const float* ln_b  = (const float*)d_in[4];
    const float* dp_w1 = (const float*)d_in[5];  const float* dp_b1 = (const float*)d_in[6];
    const float* dp_w2 = (const float*)d_in[7];  const float* dp_b2 = (const float*)d_in[8];
    const float* dp_wl = (const float*)d_in[9];  const float* dp_bl = (const float*)d_in[10];
    const float* pp_w1 = (const float*)d_in[11]; const float* pp_b1 = (const float*)d_in[12];
    const float* pp_w2 = (const float*)d_in[13]; const float* pp_b2 = (const float*)d_in[14];
    const float* pp_wl = (const float*)d_in[15]; const float* pp_bl = (const float*)d_in[16];
    const float* ep_w1 = (const float*)d_in[17]; const float* ep_b1 = (const float*)d_in[18];
    const float* ep_w2 = (const float*)d_in[19]; const float* ep_b2 = (const float*)d_in[20];
    const float* ep_wl = (const float*)d_in[21]; const float* ep_bl = (const float*)d_in[22];
    const float* np_w  = (const float*)d_in[23]; const float* np_b  = (const float*)d_in[24];

    float* out  = (float*)d_out;
    float* o_ld = out;
    float* o_du = out + R;
    float* o_pp = out + 2 * R;
    float* o_en = out + 5 * R;
    float* o_ex = out + 6 * R;
    float* o_mk = out + 6 * R + (long long)NB * TMAX * D;

    float *xp, *xn, *h1, *h2, *h3, *h4, *h5, *h6, *wt, *nxn, *nxp;
    unsigned* red; int *dint, *cumc;
    cudaGetSymbolAddress((void**)&xp,   g_xp);
    cudaGetSymbolAddress((void**)&xn,   g_xn);
    cudaGetSymbolAddress((void**)&h1,   g_h1);
    cudaGetSymbolAddress((void**)&h2,   g_h2);
    cudaGetSymbolAddress((void**)&h3,   g_h3);
    cudaGetSymbolAddress((void**)&h4,   g_h4);
    cudaGetSymbolAddress((void**)&h5,   g_h5);
    cudaGetSymbolAddress((void**)&h6,   g_h6);
    cudaGetSymbolAddress((void**)&wt,   g_wt);
    cudaGetSymbolAddress((void**)&nxn,  g_nxn);
    cudaGetSymbolAddress((void**)&nxp,  g_nxp);
    cudaGetSymbolAddress((void**)&red,  g_red);
    cudaGetSymbolAddress((void**)&dint, g_dint);
    cudaGetSymbolAddress((void**)&cumc, g_cumc);

    cudaFuncSetAttribute(conv_mma, cudaFuncAttributeMaxDynamicSharedMemorySize, CM_SMEM);

    const int WSL = KKC * F;

    // ---- main: init, then legal fork for side stream ----
    init_red<<<1, 32>>>(red);
    cudaEventRecord(g_ss.ev0, 0);
    cudaStreamWaitEvent(g_ss.s1, g_ss.ev0, 0);

    // ---- side: weight transpose (overlaps gemm_np on main) ----
    transpose_all<<<dim3((KKC * F + 255) / 256, 6), 256, 0, g_ss.s1>>>(
        dp_w1, dp_w2, pp_w1, pp_w2, ep_w1, ep_w2, wt);
    cudaEventRecord(g_ss.evW, g_ss.s1);

    // ---- main: note projection ----
    gemm_np<<<dim3(R / 128, 2), 256>>>(nph, np_w, np_b, x, xp);
    cudaEventRecord(g_ss.evF, 0);

    // ---- side: tensor branch (needs xp + wt) ----
    cudaStreamWaitEvent(g_ss.s1, g_ss.evF, 0);
    dim3 gm(R / 128, 2, 2);
    conv_mma<<<gm, 128, CM_SMEM, g_ss.s1>>>(
        xp, wt + 2 * WSL, pp_b1, h1,
        xp, wt + 4 * WSL, ep_b1, h3);
    conv_mma<<<gm, 128, CM_SMEM, g_ss.s1>>>(
        h1, wt + 3 * WSL, pp_b2, h2,
        h3, wt + 5 * WSL, ep_b2, h4);

    // ---- main: layernorm (overlaps conv_mma layer 1) ----
    ln_norm_k<<<R / 8, 256>>>(xp, ln_g, ln_b, xn, nxn, nxp, red);
    cudaEventRecord(g_ss.evL, 0);

    // side finals need red/nxp from ln_norm
    cudaStreamWaitEvent(g_ss.s1, g_ss.evL, 0);
    pp_final<<<R / 8, 256, 0, g_ss.s1>>>(h2, pp_wl, pp_bl, nxp, red, o_pp);
    ep_final<<<R / 8, 256, 0, g_ss.s1>>>(h4, ep_wl, ep_bl, o_en);
    cudaEventRecord(g_ss.evJ, g_ss.s1);

    // ---- main: duration path (fp32, exact); needs wt slots 0,1 ----
    cudaStreamWaitEvent(0, g_ss.evW, 0);
    dim3 gg(R / 128, 2);
    conv_gemm<<<gg, 256>>>(xn, wt + 0 * WSL, dp_b1, h5);
    conv_gemm<<<gg, 256>>>(h5, wt + 1 * WSL, dp_b2, h6);
    dp_final<<<R / 8, 256>>>(h6, dp_wl, dp_bl, nxn, red, o_ld, o_du, dint);
    cumsum_k<<<NB, 1024>>>(dint, cumc);
    expand_k<<<dim3(TMAX / 128, NB), 256>>>(xp, cumc, o_ex, o_mk);

    // ---- join ----
    cudaStreamWaitEvent(0, g_ss.evJ, 0);
}

// round 15
// speedup vs baseline: 1.0108x; 1.0108x over previous
#include <cuda_runtime.h>
#include <math.h>
#include <stdint.h>

#define R    16384      // B*S rows
#define D    256
#define F    256
#define NB   16
#define TMAX 8192
#define KKC  768        // 3 * 256 im2col K

typedef unsigned long long u64;

// ---------------- scratch (static device allocations only) ----------------
__device__ float g_xp[R * D];
__device__ float g_xn[R * D];
__device__ float g_h1[R * F];
__device__ float g_h2[R * F];
__device__ float g_h3[R * F];
__device__ float g_h4[R * F];
__device__ float g_h5[R * F];
__device__ float g_h6[R * F];
__device__ float g_wt[6 * KKC * F];
__device__ float g_nxn[R];
__device__ float g_nxp[R];
__device__ unsigned g_red[3];
__device__ int   g_dint[R];
__device__ int   g_cumc[R];

// ---------------- host-side stream/event resources (created pre-run) -------
struct SideStream {
    cudaStream_t s1;
    cudaEvent_t ev0, evF, evH, evJ, evL;
    SideStream() {
        cudaStreamCreateWithFlags(&s1, cudaStreamNonBlocking);
        cudaEventCreateWithFlags(&ev0, cudaEventDisableTiming);
        cudaEventCreateWithFlags(&evF, cudaEventDisableTiming);
        cudaEventCreateWithFlags(&evH, cudaEventDisableTiming);
        cudaEventCreateWithFlags(&evJ, cudaEventDisableTiming);
        cudaEventCreateWithFlags(&evL, cudaEventDisableTiming);
    }
};
static SideStream g_ss;

// =================== portable PTX helpers ==================================
__device__ __forceinline__ uint32_t smem_u32(const void* p) {
    uint32_t a;
    asm("{ .reg .u64 t; cvta.to.shared.u64 t, %1; cvt.u32.u64 %0, t; }" : "=r"(a) : "l"(p));
    return a;
}
__device__ __forceinline__ void cp_async16(uint32_t dst, const void* src, uint32_t srcsize) {
    asm volatile("cp.async.cg.shared.global [%0], [%1], 16, %2;"
                 :: "r"(dst), "l"(src), "r"(srcsize) : "memory");
}
#define CP_COMMIT() asm volatile("cp.async.commit_group;" ::: "memory")
#define CP_WAIT1()  asm volatile("cp.async.wait_group 1;" ::: "memory")
#define CP_WAIT0()  asm volatile("cp.async.wait_group 0;" ::: "memory")
__device__ __forceinline__ uint32_t lds32(uint32_t addr) {
    uint32_t v;
    asm volatile("ld.shared.b32 %0, [%1];" : "=r"(v) : "r"(addr));
    return v;
}
__device__ __forceinline__ void mma_tf32(float* c, const uint32_t* a, const uint32_t* b) {
    asm volatile("mma.sync.aligned.m16n8k8.row.col.f32.tf32.tf32.f32 "
                 "{%0,%1,%2,%3}, {%4,%5,%6,%7}, {%8,%9}, {%0,%1,%2,%3};"
                 : "+f"(c[0]), "+f"(c[1]), "+f"(c[2]), "+f"(c[3])
                 : "r"(a[0]), "r"(a[1]), "r"(a[2]), "r"(a[3]), "r"(b[0]), "r"(b[1]));
}
// ---- packed fp32x2 FMA (harmless if lowered to 2x FFMA) -------------------
__device__ __forceinline__ u64 pk2(float x) {
    u64 r; uint32_t xi = __float_as_uint(x);
    asm("mov.b64 %0, {%1, %1};" : "=l"(r) : "r"(xi));
    return r;
}
__device__ __forceinline__ void fma2(u64& acc, u64 a, u64 b) {
    asm("fma.rn.f32x2 %0, %1, %2, %0;" : "+l"(acc) : "l"(a), "l"(b));
}
__device__ __forceinline__ float2 up2(u64 v) {
    float2 f; uint32_t lo, hi;
    asm("mov.b64 {%0, %1}, %2;" : "=r"(lo), "=r"(hi) : "l"(v));
    f.x = __uint_as_float(lo); f.y = __uint_as_float(hi);
    return f;
}

// ---------------- init global reduction cells ------------------------------
__global__ void init_red(unsigned* red) {
    if (threadIdx.x == 0) { red[0] = 0u; red[1] = 0x7F800000u; red[2] = 0u; }
}

// ---------------- fused weight transpose -----------------------------------
__global__ void transpose_all(const float* __restrict__ dp1, const float* __restrict__ dp2,
                              const float* __restrict__ pp1, const float* __restrict__ pp2,
                              const float* __restrict__ ep1, const float* __restrict__ ep2,
                              float* __restrict__ wt)
{
    int y = blockIdx.y;
    const float* src = (y == 0) ? dp1 : (y == 1) ? dp2 : (y == 2) ? pp1 : (y == 3) ? pp2 : (y == 4) ? ep1 : ep2;
    float* dst = wt + y * (KKC * F);
    int idx = blockIdx.x * 256 + threadIdx.x;
    if (idx >= KKC * F) return;
    if (y < 2) {
        int f = idx & 255, kc = idx >> 8;
        int k = kc >> 8, c = kc & 255;
        dst[idx] = src[(f * 256 + c) * 3 + k];
    } else {
        int f = idx / KKC, kk = idx - f * KKC;
        int k = kk >> 8, c = kk & 255;
        dst[idx] = src[(f * 256 + c) * 3 + k];
    }
}

// ---------------- note-projection GEMM (fp32, exact) -----------------------
// Operates on an M-slice: caller passes offset base pointers, grid.x = rows/128.
__global__ __launch_bounds__(256) void gemm_np(
    const float* __restrict__ A, const float* __restrict__ W,
    const float* __restrict__ bias, const float* __restrict__ Xadd,
    float* __restrict__ C)
{
    __shared__ float As[8][128];
    __shared__ float Bs[8][128];
    const int bm = blockIdx.x * 128, bn = blockIdx.y * 128;
    const int tid  = threadIdx.x;
    const int arow = tid >> 1,  acol = (tid & 1) << 2;
    const int brow = tid >> 5,  bcol = (tid & 31) << 2;
    const int ty = (tid >> 4) << 3, tx = (tid & 15) << 3;
    u64 acc2[8][4] = {};
    for (int k0 = 0; k0 < 256; k0 += 8) {
        float4 av = *reinterpret_cast<const float4*>(&A[(bm + arow) * 256 + k0 + acol]);
        float4 bv = *reinterpret_cast<const float4*>(&W[(k0 + brow) * 256 + bn + bcol]);
        __syncthreads();
        As[acol + 0][arow] = av.x; As[acol + 1][arow] = av.y;
        As[acol + 2][arow] = av.z; As[acol + 3][arow] = av.w;
        *reinterpret_cast<float4*>(&Bs[brow][bcol]) = bv;
        __syncthreads();
#pragma unroll
        for (int k = 0; k < 8; k++) {
            float a[8];
            *(float4*)&a[0] = *(const float4*)&As[k][ty];
            *(float4*)&a[4] = *(const float4*)&As[k][ty + 4];
            u64 ap[8];
#pragma unroll
            for (int i = 0; i < 8; i++) ap[i] = pk2(a[i]);
            const u64* b64 = reinterpret_cast<const u64*>(&Bs[k][tx]);
            u64 bp[4];
#pragma unroll
            for (int j = 0; j < 4; j++) bp[j] = b64[j];
#pragma unroll
            for (int i = 0; i < 8; i++)
#pragma unroll
                for (int j = 0; j < 4; j++) fma2(acc2[i][j], ap[i], bp[j]);
        }
    }
#pragma unroll
    for (int i = 0; i < 8; i++) {
        const int mo = (bm + ty + i) * 256 + bn + tx;
#pragma unroll
        for (int j = 0; j < 4; j += 2) {
            float2 p0 = up2(acc2[i][j]), p1 = up2(acc2[i][j + 1]);
            float4 xv = *reinterpret_cast<const float4*>(&Xadd[mo + 2 * j]);
            float4 o;
            o.x = p0.x + xv.x + bias[bn + tx + 2 * j + 0];
            o.y = p0.y + xv.y + bias[bn + tx + 2 * j + 1];
            o.z = p1.x + xv.z + bias[bn + tx + 2 * j + 2];
            o.w = p1.y + xv.w + bias[bn + tx + 2 * j + 3];
            *reinterpret_cast<float4*>(&C[mo + 2 * j]) = o;
        }
    }
}

// ---------------- conv1d GEMM fp32 (duration path — exact), 128x128 tile ---
// R10-proven version: 2 syncs per BK=8 chunk.
__global__ __launch_bounds__(256) void conv_gemm(
    const float* __restrict__ A, const float* __restrict__ Wt,
    const float* __restrict__ bias, float* __restrict__ C)
{
    __shared__ float As[8][128];
    __shared__ float Bs[8][128];
    const int bm = blockIdx.x * 128, bn = blockIdx.y * 128;
    const int tid  = threadIdx.x;
    const int arow = tid >> 1,  acol = (tid & 1) << 2;
    const int brow = tid >> 5,  bcol = (tid & 31) << 2;
    const int ty = (tid >> 4) << 3, tx = (tid & 15) << 3;
    const int m = bm + arow;
    const int bb = m >> 10, s = m & 1023;
    const float* Abase = A + (bb << 10) * D;
    u64 acc2[8][4] = {};
    for (int k0 = 0; k0 < KKC; k0 += 8) {
        const int tap = k0 >> 8;
        const int sr  = s + tap - 1;
        const int c0  = (k0 & 255) + acol;
        float4 av = make_float4(0.f, 0.f, 0.f, 0.f);
        if ((unsigned)sr < 1024u)
            av = *reinterpret_cast<const float4*>(Abase + sr * D + c0);
        float4 bv = *reinterpret_cast<const float4*>(&Wt[(k0 + brow) * F + bn + bcol]);
        __syncthreads();
        As[acol + 0][arow] = av.x; As[acol + 1][arow] = av.y;
        As[acol + 2][arow] = av.z; As[acol + 3][arow] = av.w;
        *reinterpret_cast<float4*>(&Bs[brow][bcol]) = bv;
        __syncthreads();
#pragma unroll
        for (int k = 0; k < 8; k++) {
            float a[8];
            *(float4*)&a[0] = *(const float4*)&As[k][ty];
            *(float4*)&a[4] = *(const float4*)&As[k][ty + 4];
            u64 ap[8];
#pragma unroll
            for (int i = 0; i < 8; i++) ap[i] = pk2(a[i]);
            const u64* b64 = reinterpret_cast<const u64*>(&Bs[k][tx]);
            u64 bp[4];
#pragma unroll
            for (int j = 0; j < 4; j++) bp[j] = b64[j];
#pragma unroll
            for (int i = 0; i < 8; i++)
#pragma unroll
                for (int j = 0; j < 4; j++) fma2(acc2[i][j], ap[i], bp[j]);
        }
    }
#pragma unroll
    for (int i = 0; i < 8; i++) {
        const int mo = (bm + ty + i) * F + bn + tx;
#pragma unroll
        for (int j = 0; j < 4; j += 2) {
            float2 p0 = up2(acc2[i][j]), p1 = up2(acc2[i][j + 1]);
            float4 o;
            o.x = fmaxf(p0.x + bias[bn + tx + 2 * j + 0], 0.f);
            o.y = fmaxf(p0.y + bias[bn + tx + 2 * j + 1], 0.f);
            o.z = fmaxf(p1.x + bias[bn + tx + 2 * j + 2], 0.f);
            o.w = fmaxf(p1.y + bias[bn + tx + 2 * j + 3], 0.f);
            *reinterpret_cast<float4*>(&C[mo + 2 * j]) = o;
        }
    }
}

// ---------------- conv1d GEMM via mma.sync tf32 (pitch/energy) -------------
// R10-proven config: 128 threads, 4 warps (2x2) at 64x64, BK=32 double buffer.
#define CCH      24
#define ASTRIDE  36
#define ATILE_B  (128 * ASTRIDE * 4)
#define STG_B    (2 * ATILE_B)
#define CM_SMEM  (2 * STG_B)               // 73728

__global__ __launch_bounds__(128) void conv_mma(
    const float* __restrict__ in0, const float* __restrict__ w0,
    const float* __restrict__ b0p, float* __restrict__ out0,
    const float* __restrict__ in1, const float* __restrict__ w1,
    const float* __restrict__ b1p, float* __restrict__ out1)
{
    extern __shared__ float smf[];
    const float* in  = (blockIdx.z == 0) ? in0 : in1;
    const float* wB  = (blockIdx.z == 0) ? w0  : w1;
    const float* bia = (blockIdx.z == 0) ? b0p : b1p;
    float* out       = (blockIdx.z == 0) ? out0 : out1;

    const int tid = threadIdx.x, lane = tid & 31, wid = tid >> 5;
    const int wm = wid >> 1, wn = wid & 1;
    const int g = lane >> 2, t = lane & 3;

    const int bm = blockIdx.x * 128, bn = blockIdx.y * 128;
    const int bb = bm >> 10, s0 = bm & 1023;
    const float* Abase = in + (bb << 10) * D;

    const uint32_t sbase = smem_u32(smf);
    float acc[4][8][4] = {};

    auto fill = [&](int ch, int st) {
        const int tap = ch >> 3;
        const int c0  = (ch & 7) * 32;
        const uint32_t aS = sbase + st * STG_B;
        const uint32_t bS = aS + ATILE_B;
#pragma unroll
        for (int i = 0; i < 8; i++) {
            int idx = i * 128 + tid;
            int r = idx >> 3, j = idx & 7;
            int sr = s0 + r + tap - 1;
            uint32_t ok = ((unsigned)sr < 1024u) ? 16u : 0u;
            const float* gp = Abase + (ok ? sr : 0) * D + c0 + j * 4;
            cp_async16(aS + (uint32_t)(r * ASTRIDE + j * 4) * 4, gp, ok);
        }
#pragma unroll
        for (int i = 0; i < 8; i++) {
            int idx = i * 128 + tid;
            int r = idx >> 3, j = idx & 7;
            const float* gp = wB + (bn + r) * KKC + tap * 256 + c0 + j * 4;
            cp_async16(bS + (uint32_t)(r * ASTRIDE + j * 4) * 4, gp, 16u);
        }
    };

    fill(0, 0);
    CP_COMMIT();

    for (int ch = 0; ch < CCH; ch++) {
        __syncthreads();
        if (ch + 1 < CCH) {
            fill(ch + 1, (ch + 1) & 1);
            CP_COMMIT();
            CP_WAIT1();
        } else {
            CP_WAIT0();
        }
        __syncthreads();

        const uint32_t aS = sbase + (ch & 1) * STG_B;
        const uint32_t bS = aS + ATILE_B;
#pragma unroll
        for (int ks = 0; ks < 4; ks++) {
            const int kb = ks * 8;
            uint32_t afr[4][4], bfr[8][2];
#pragma unroll
            for (int mt = 0; mt < 4; mt++) {
                uint32_t ab = aS + (uint32_t)((wm * 64 + mt * 16 + g) * ASTRIDE + kb + t) * 4;
                afr[mt][0] = lds32(ab);
                afr[mt][1] = lds32(ab + 8 * ASTRIDE * 4);
                afr[mt][2] = lds32(ab + 16);
                afr[mt][3] = lds32(ab + 8 * ASTRIDE * 4 + 16);
            }
#pragma unroll
            for (int nt = 0; nt < 8; nt++) {
                uint32_t bb2 = bS + (uint32_t)((wn * 64 + nt * 8 + g) * ASTRIDE + kb + t) * 4;
                bfr[nt][0] = lds32(bb2);
                bfr[nt][1] = lds32(bb2 + 16);
            }
#pragma unroll
            for (int mt = 0; mt < 4; mt++)
#pragma unroll
                for (int nt = 0; nt < 8; nt++)
                    mma_tf32(acc[mt][nt], afr[mt], bfr[nt]);
        }
    }

#pragma unroll
    for (int nt = 0; nt < 8; nt++) {
        const int col = bn + wn * 64 + nt * 8 + 2 * t;
        const float bv0 = bia[col], bv1 = bia[col + 1];
#pragma unroll
        for (int mt = 0; mt < 4; mt++) {
            const int row0 = bm + wm * 64 + mt * 16 + g;
            float2 v0, v1;
            v0.x = fmaxf(acc[mt][nt][0] + bv0, 0.f);
            v0.y = fmaxf(acc[mt][nt][1] + bv1, 0.f);
            v1.x = fmaxf(acc[mt][nt][2] + bv0, 0.f);
            v1.y = fmaxf(acc[mt][nt][3] + bv1, 0.f);
            *reinterpret_cast<float2*>(out + row0 * F + col) = v0;
            *reinterpret_cast<float2*>(out + (row0 + 8) * F + col) = v1;
        }
    }
}

// ---------------- layernorm + row norms + fused global reductions ----------
__global__ void ln_norm_k(const float* __restrict__ xp, const float* __restrict__ g,
                          const float* __restrict__ bta, float* __restrict__ xn,
                          float* __restrict__ nxn, float* __restrict__ nxp,
                          unsigned* __restrict__ red)
{
    int row  = blockIdx.x * 8 + (threadIdx.x >> 5);
    int lane = threadIdx.x & 31;
    const float* xr = xp + row * D;
    float v[8], s = 0.f;
#pragma unroll
    for (int i = 0; i < 8; i++) { v[i] = xr[lane + 32 * i]; s += v[i]; }
#pragma unroll
    for (int o = 16; o > 0; o >>= 1) s += __shfl_xor_sync(0xffffffffu, s, o);
    float mean = s * (1.f / 256.f);
    float sq = 0.f, sp = 0.f;
#pragma unroll
    for (int i = 0; i < 8; i++) { float d = v[i] - mean; sq += d * d; sp += v[i] * v[i]; }
#pragma unroll
    for (int o = 16; o > 0; o >>= 1) {
        sq += __shfl_xor_sync(0xffffffffu, sq, o);
        sp += __shfl_xor_sync(0xffffffffu, sp, o);
    }
    float r = 1.0f / sqrtf(sq * (1.f / 256.f) + 1e-5f);
    float n2 = 0.f;
#pragma unroll
    for (int i = 0; i < 8; i++) {
        float y = g[lane + 32 * i] * (v[i] - mean) * r + bta[lane + 32 * i];
        xn[row * D + lane + 32 * i] = y;
        n2 += y * y;
    }
#pragma unroll
    for (int o = 16; o > 0; o >>= 1) n2 += __shfl_xor_sync(0xffffffffu, n2, o);
    __shared__ float rn[8], rp[8];
    float vn = sqrtf(n2), vp = sqrtf(sp);
    if (lane == 0) {
        nxn[row] = vn; nxp[row] = vp;
        rn[threadIdx.x >> 5] = vn; rp[threadIdx.x >> 5] = vp;
    }
    __syncthreads();
    if (threadIdx.x == 0) {
        float m1 = rn[0], mn2 = rp[0], m2 = rp[0];
#pragma unroll
        for (int i = 1; i < 8; i++) {
            m1 = fmaxf(m1, rn[i]);
            mn2 = fminf(mn2, rp[i]); m2 = fmaxf(m2, rp[i]);
        }
        atomicMax(&red[0], __float_as_uint(m1));
        atomicMin(&red[1], __float_as_uint(mn2));
        atomicMax(&red[2], __float_as_uint(m2));
    }
}

// ---------------- heads ----------------------------------------------------
__global__ void dp_final(const float* __restrict__ h2, const float* __restrict__ wl,
                         const float* __restrict__ blp, const float* __restrict__ nxn,
                         const unsigned* __restrict__ red, float* __restrict__ o_ld,
                         float* __restrict__ o_du, int* __restrict__ dint)
{
    int row  = blockIdx.x * 8 + (threadIdx.x >> 5);
    int lane = threadIdx.x & 31;
    const float* hr = h2 + row * F;
    float dot = 0.f;
#pragma unroll
    for (int i = 0; i < 8; i++) dot += hr[lane + 32 * i] * wl[lane + 32 * i];
#pragma unroll
    for (int o = 16; o > 0; o >>= 1) dot += __shfl_xor_sync(0xffffffffu, dot, o);
    if (lane == 0) {
        float base = dot + blp[0];
        float es = 0.8f + 0.4f * (nxn[row] / __uint_as_float(red[0]));
        int s = row & 1023;
        float ps = 1.0f + 0.1f * ((float)s / 1024.0f);
        float ld = (base * es) * ps;
        o_ld[row] = ld;
        float dur = expf(ld);
        o_du[row] = dur;
        dint[row] = (int)rintf(dur);
    }
}

__global__ void pp_final(const float* __restrict__ h2, const float* __restrict__ wl,
                         const float* __restrict__ blp, const float* __restrict__ nxp,
                         const unsigned* __restrict__ red, float* __restrict__ o)
{
    int row  = blockIdx.x * 8 + (threadIdx.x >> 5);
    int lane = threadIdx.x & 31;
    const float* hr = h2 + row * F;
    float d0 = 0.f, d1 = 0.f, d2 = 0.f;
#pragma unroll
    for (int i = 0; i < 8; i++) {
        float h = hr[lane + 32 * i];
        const float* w = wl + (lane + 32 * i) * 3;
        d0 += h * w[0]; d1 += h * w[1]; d2 += h * w[2];
    }
#pragma unroll
    for (int o2 = 16; o2 > 0; o2 >>= 1) {
        d0 += __shfl_xor_sync(0xffffffffu, d0, o2);
        d1 += __shfl_xor_sync(0xffffffffu, d1, o2);
        d2 += __shfl_xor_sync(0xffffffffu, d2, o2);
    }
    if (lane == 0) {
        float p0 = d0 + blp[0], p1 = d1 + blp[1], p2 = d2 + blp[2];
        float mn = __uint_as_float(red[1]), mx = __uint_as_float(red[2]);
        float en = (nxp[row] - mn) / (mx - mn + 1e-8f);
        float f0s = 100.f + 400.f * en;
        float f0b = expf(p0) * f0s / 220.f;
        o[row * 3 + 0] = logf(f0b + 1e-8f);
        o[row * 3 + 1] = p1;
        o[row * 3 + 2] = p2;
    }
}

__global__ void ep_final(const float* __restrict__ h2, const float* __restrict__ wl,
                         const float* __restrict__ blp, float* __restrict__ o)
{
    int row  = blockIdx.x * 8 + (threadIdx.x >> 5);
    int lane = threadIdx.x & 31;
    const float* hr = h2 + row * F;
    float dot = 0.f;
#pragma unroll
    for (int i = 0; i < 8; i++) dot += hr[lane + 32 * i] * wl[lane + 32 * i];
#pragma unroll
    for (int o2 = 16; o2 > 0; o2 >>= 1) dot += __shfl_xor_sync(0xffffffffu, dot, o2);
    if (lane == 0) o[row] = dot + blp[0];
}

// ---------------- per-batch inclusive scan + clip (warp scan) --------------
__global__ void cumsum_k(const int* __restrict__ dint, int* __restrict__ cumc) {
    int b = blockIdx.x, t = threadIdx.x;
    int lane = t & 31, w = t >> 5;
    int s = dint[b * 1024 + t];
#pragma unroll
    for (int o = 1; o < 32; o <<= 1) {
        int u = __shfl_up_sync(0xffffffffu, s, o);
        if (lane >= o) s += u;
    }
    __shared__ int ws[32];
    if (lane == 31) ws[w] = s;
    __syncthreads();
    if (w == 0) {
        int x = ws[lane];
#pragma unroll
        for (int o = 1; o < 32; o <<= 1) {
            int u = __shfl_up_sync(0xffffffffu, x, o);
            if (lane >= o) x += u;
        }
        ws[lane] = x;
    }
    __syncthreads();
    int base = (w > 0) ? ws[w - 1] : 0;
    cumc[b * 1024 + t] = min(s + base, TMAX);
}

// ---------------- length regulation ----------------------------------------
__global__ __launch_bounds__(256) void expand_k(
    const float* __restrict__ xp, const int* __restrict__ cumc,
    float* __restrict__ o_exp, float* __restrict__ o_msk)
{
    __shared__ int cs[1024];
    __shared__ int idxs[128];
    int b  = blockIdx.y;
    int t0 = blockIdx.x * 128;
    int tid = threadIdx.x;
    for (int i = tid; i < 1024; i += 256) cs[i] = cumc[b * 1024 + i];
    __syncthreads();
    int cend = cs[1023];
    if (tid < 128) {
        int t = t0 + tid;
        int lo = 0, hi = 1024;
        while (lo < hi) { int mid = (lo + hi) >> 1; if (cs[mid] <= t) lo = mid + 1; else hi = mid; }
        bool mask = (t >= cend);
        idxs[tid] = mask ? -1 : min(lo, 1023);
        o_msk[b * TMAX + t] = mask ? 1.0f : 0.0f;
    }
    __syncthreads();
    const float* xb = xp + (b << 10) * D;
    float* ob = o_exp + ((long long)b * TMAX + t0) * D;
    for (int i = tid; i < 128 * 64; i += 256) {
        int fr = i >> 6, c4 = (i & 63) << 2;
        int id = idxs[fr];
        float4 v = make_float4(0.f, 0.f, 0.f, 0.f);
        if (id >= 0) v = *reinterpret_cast<const float4*>(xb + id * D + c4);
        *reinterpret_cast<float4*>(ob + (long long)fr * D + c4) = v;
    }
}

// ---------------- host orchestration ---------------------------------------
extern "C" void kernel_launch(void* const* d_in, const int* in_sizes, int n_in,
                              void* d_out, int out_size)
{
    const float* x     = (const float*)d_in[0];
    const float* nph   = (const float*)d_in[2];
    const float* ln_g  = (const float*)d_in[3];
    const float* ln_b  = (const float*)d_in[4];
    const float* dp_w1 = (const float*)d_in[5];  const float* dp_b1 = (const float*)d_in[6];
    const float* dp_w2 = (const float*)d_in[7];  const float* dp_b2 = (const float*)d_in[8];
    const float* dp_wl = (const float*)d_in[9];  const float* dp_bl = (const float*)d_in[10];
    const float* pp_w1 = (const float*)d_in[11]; const float* pp_b1 = (const float*)d_in[12];
    const float* pp_w2 = (const float*)d_in[13]; const float* pp_b2 = (const float*)d_in[14];
    const float* pp_wl = (const float*)d_in[15]; const float* pp_bl = (const float*)d_in[16];
    const float* ep_w1 = (const float*)d_in[17]; const float* ep_b1 = (const float*)d_in[18];
    const float* ep_w2 = (const float*)d_in[19]; const float* ep_b2 = (const float*)d_in[20];
    const float* ep_wl = (const float*)d_in[21]; const float* ep_bl = (const float*)d_in[22];
    const float* np_w  = (const float*)d_in[23]; const float* np_b  = (const float*)d_in[24];

    float* out  = (float*)d_out;
    float* o_ld = out;
    float* o_du = out + R;
    float* o_pp = out + 2 * R;
    float* o_en = out + 5 * R;
    float* o_ex = out + 6 * R;
    float* o_mk = out + 6 * R + (long long)NB * TMAX * D;

    float *xp, *xn, *h1, *h2, *h3, *h4, *h5, *h6, *wt, *nxn, *nxp;
    unsigned* red; int *dint, *cumc;
    cudaGetSymbolAddress((void**)&xp,   g_xp);
    cudaGetSymbolAddress((void**)&xn,   g_xn);
    cudaGetSymbolAddress((void**)&h1,   g_h1);
    cudaGetSymbolAddress((void**)&h2,   g_h2);
    cudaGetSymbolAddress((void**)&h3,   g_h3);
    cudaGetSymbolAddress((void**)&h4,   g_h4);
    cudaGetSymbolAddress((void**)&h5,   g_h5);
    cudaGetSymbolAddress((void**)&h6,   g_h6);
    cudaGetSymbolAddress((void**)&wt,   g_wt);
    cudaGetSymbolAddress((void**)&nxn,  g_nxn);
    cudaGetSymbolAddress((void**)&nxp,  g_nxp);
    cudaGetSymbolAddress((void**)&red,  g_red);
    cudaGetSymbolAddress((void**)&dint, g_dint);
    cudaGetSymbolAddress((void**)&cumc, g_cumc);

    cudaFuncSetAttribute(conv_mma, cudaFuncAttributeMaxDynamicSharedMemorySize, CM_SMEM);

    const int WSL = KKC * F;
    const int HALF = R / 2;                 // 8192 rows per gemm_np half

    // ---- main: init, then legal fork for side stream ----
    init_red<<<1, 32>>>(red);
    cudaEventRecord(g_ss.ev0, 0);
    cudaStreamWaitEvent(g_ss.s1, g_ss.ev0, 0);

    // ---- side: weight transpose, then second half of note projection ----
    transpose_all<<<dim3((KKC * F + 255) / 256, 6), 256, 0, g_ss.s1>>>(
        dp_w1, dp_w2, pp_w1, pp_w2, ep_w1, ep_w2, wt);
    gemm_np<<<dim3(HALF / 128, 2), 256, 0, g_ss.s1>>>(
        nph + (long long)HALF * D, np_w, np_b, x + (long long)HALF * D, xp + (long long)HALF * D);
    cudaEventRecord(g_ss.evH, g_ss.s1);

    // ---- main: first half of note projection ----
    gemm_np<<<dim3(HALF / 128, 2), 256>>>(nph, np_w, np_b, x, xp);
    cudaEventRecord(g_ss.evF, 0);

    // ---- side: tensor branch (needs full xp: own half + main's via evF) ----
    cudaStreamWaitEvent(g_ss.s1, g_ss.evF, 0);
    dim3 gm(R / 128, 2, 2);
    conv_mma<<<gm, 128, CM_SMEM, g_ss.s1>>>(
        xp, wt + 2 * WSL, pp_b1, h1,
        xp, wt + 4 * WSL, ep_b1, h3);
    conv_mma<<<gm, 128, CM_SMEM, g_ss.s1>>>(
        h1, wt + 3 * WSL, pp_b2, h2,
        h3, wt + 5 * WSL, ep_b2, h4);

    // ---- main: layernorm (needs full xp: own half + side's via evH) ----
    cudaStreamWaitEvent(0, g_ss.evH, 0);
    ln_norm_k<<<R / 8, 256>>>(xp, ln_g, ln_b, xn, nxn, nxp, red);
    cudaEventRecord(g_ss.evL, 0);

    // side finals need red/nxp from ln_norm
    cudaStreamWaitEvent(g_ss.s1, g_ss.evL, 0);
    pp_final<<<R / 8, 256, 0, g_ss.s1>>>(h2, pp_wl, pp_bl, nxp, red, o_pp);
    ep_final<<<R / 8, 256, 0, g_ss.s1>>>(h4, ep_wl, ep_bl, o_en);
    cudaEventRecord(g_ss.evJ, g_ss.s1);

    // ---- main: duration path (fp32, exact); wt ordered via evH ----
    dim3 gg(R / 128, 2);
    conv_gemm<<<gg, 256>>>(xn, wt + 0 * WSL, dp_b1, h5);
    conv_gemm<<<gg, 256>>>(h5, wt + 1 * WSL, dp_b2, h6);
    dp_final<<<R / 8, 256>>>(h6, dp_wl, dp_bl, nxn, red, o_ld, o_du, dint);
    cumsum_k<<<NB, 1024>>>(dint, cumc);
    expand_k<<<dim3(TMAX / 128, NB), 256>>>(xp, cumc, o_ex, o_mk);

    // ---- join ----
    cudaStreamWaitEvent(0, g_ss.evJ, 0);
}

// round 16
// speedup vs baseline: 1.0125x; 1.0017x over previous
#include <cuda_runtime.h>
#include <math.h>
#include <stdint.h>

#define R    16384      // B*S rows
#define D    256
#define F    256
#define NB   16
#define TMAX 8192
#define KKC  768        // 3 * 256 im2col K

typedef unsigned long long u64;

// ---------------- scratch (static device allocations only) ----------------
__device__ float g_xp[R * D];
__device__ float g_xn[R * D];
__device__ float g_h1[R * F];
__device__ float g_h2[R * F];
__device__ float g_h3[R * F];
__device__ float g_h4[R * F];
__device__ float g_h5[R * F];
__device__ float g_h6[R * F];
__device__ float g_wt[6 * KKC * F];
__device__ float g_nxn[R];
__device__ float g_nxp[R];
__device__ unsigned g_red[3];
__device__ int   g_dint[R];
__device__ int   g_cumc[R];

// ---------------- host-side stream/event resources (created pre-run) -------
// Side stream created at the LOWEST priority so the duration-path (critical
// path, default stream) wins SM scheduling whenever both are resident.
struct SideStream {
    cudaStream_t s1;
    cudaEvent_t ev0, evF, evJ, evW, evL;
    SideStream() {
        int leastP = 0, greatestP = 0;
        cudaDeviceGetStreamPriorityRange(&leastP, &greatestP);
        cudaStreamCreateWithPriority(&s1, cudaStreamNonBlocking, leastP);
        cudaEventCreateWithFlags(&ev0, cudaEventDisableTiming);
        cudaEventCreateWithFlags(&evF, cudaEventDisableTiming);
        cudaEventCreateWithFlags(&evJ, cudaEventDisableTiming);
        cudaEventCreateWithFlags(&evW, cudaEventDisableTiming);
        cudaEventCreateWithFlags(&evL, cudaEventDisableTiming);
    }
};
static SideStream g_ss;

// =================== portable PTX helpers ==================================
__device__ __forceinline__ uint32_t smem_u32(const void* p) {
    uint32_t a;
    asm("{ .reg .u64 t; cvta.to.shared.u64 t, %1; cvt.u32.u64 %0, t; }" : "=r"(a) : "l"(p));
    return a;
}
__device__ __forceinline__ void cp_async16(uint32_t dst, const void* src, uint32_t srcsize) {
    asm volatile("cp.async.cg.shared.global [%0], [%1], 16, %2;"
                 :: "r"(dst), "l"(src), "r"(srcsize) : "memory");
}
#define CP_COMMIT() asm volatile("cp.async.commit_group;" ::: "memory")
#define CP_WAIT1()  asm volatile("cp.async.wait_group 1;" ::: "memory")
#define CP_WAIT0()  asm volatile("cp.async.wait_group 0;" ::: "memory")
__device__ __forceinline__ uint32_t lds32(uint32_t addr) {
    uint32_t v;
    asm volatile("ld.shared.b32 %0, [%1];" : "=r"(v) : "r"(addr));
    return v;
}
__device__ __forceinline__ void mma_tf32(float* c, const uint32_t* a, const uint32_t* b) {
    asm volatile("mma.sync.aligned.m16n8k8.row.col.f32.tf32.tf32.f32 "
                 "{%0,%1,%2,%3}, {%4,%5,%6,%7}, {%8,%9}, {%0,%1,%2,%3};"
                 : "+f"(c[0]), "+f"(c[1]), "+f"(c[2]), "+f"(c[3])
                 : "r"(a[0]), "r"(a[1]), "r"(a[2]), "r"(a[3]), "r"(b[0]), "r"(b[1]));
}
// ---- packed fp32x2 FMA (harmless if lowered to 2x FFMA) -------------------
__device__ __forceinline__ u64 pk2(float x) {
    u64 r; uint32_t xi = __float_as_uint(x);
    asm("mov.b64 %0, {%1, %1};" : "=l"(r) : "r"(xi));
    return r;
}
__device__ __forceinline__ void fma2(u64& acc, u64 a, u64 b) {
    asm("fma.rn.f32x2 %0, %1, %2, %0;" : "+l"(acc) : "l"(a), "l"(b));
}
__device__ __forceinline__ float2 up2(u64 v) {
    float2 f; uint32_t lo, hi;
    asm("mov.b64 {%0, %1}, %2;" : "=r"(lo), "=r"(hi) : "l"(v));
    f.x = __uint_as_float(lo); f.y = __uint_as_float(hi);
    return f;
}

// ---------------- init global reduction cells ------------------------------
__global__ void init_red(unsigned* red) {
    if (threadIdx.x == 0) { red[0] = 0u; red[1] = 0x7F800000u; red[2] = 0u; }
}

// ---------------- fused weight transpose -----------------------------------
__global__ void transpose_all(const float* __restrict__ dp1, const float* __restrict__ dp2,
                              const float* __restrict__ pp1, const float* __restrict__ pp2,
                              const float* __restrict__ ep1, const float* __restrict__ ep2,
                              float* __restrict__ wt)
{
    int y = blockIdx.y;
    const float* src = (y == 0) ? dp1 : (y == 1) ? dp2 : (y == 2) ? pp1 : (y == 3) ? pp2 : (y == 4) ? ep1 : ep2;
    float* dst = wt + y * (KKC * F);
    int idx = blockIdx.x * 256 + threadIdx.x;
    if (idx >= KKC * F) return;
    if (y < 2) {
        int f = idx & 255, kc = idx >> 8;
        int k = kc >> 8, c = kc & 255;
        dst[idx] = src[(f * 256 + c) * 3 + k];
    } else {
        int f = idx / KKC, kk = idx - f * KKC;
        int k = kk >> 8, c = kk & 255;
        dst[idx] = src[(f * 256 + c) * 3 + k];
    }
}

// ---------------- note-projection GEMM (fp32, exact) -----------------------
__global__ __launch_bounds__(256) void gemm_np(
    const float* __restrict__ A, const float* __restrict__ W,
    const float* __restrict__ bias, const float* __restrict__ Xadd,
    float* __restrict__ C)
{
    __shared__ float As[8][128];
    __shared__ float Bs[8][128];
    const int bm = blockIdx.x * 128, bn = blockIdx.y * 128;
    const int tid  = threadIdx.x;
    const int arow = tid >> 1,  acol = (tid & 1) << 2;
    const int brow = tid >> 5,  bcol = (tid & 31) << 2;
    const int ty = (tid >> 4) << 3, tx = (tid & 15) << 3;
    u64 acc2[8][4] = {};
    for (int k0 = 0; k0 < 256; k0 += 8) {
        float4 av = *reinterpret_cast<const float4*>(&A[(bm + arow) * 256 + k0 + acol]);
        float4 bv = *reinterpret_cast<const float4*>(&W[(k0 + brow) * 256 + bn + bcol]);
        __syncthreads();
        As[acol + 0][arow] = av.x; As[acol + 1][arow] = av.y;
        As[acol + 2][arow] = av.z; As[acol + 3][arow] = av.w;
        *reinterpret_cast<float4*>(&Bs[brow][bcol]) = bv;
        __syncthreads();
#pragma unroll
        for (int k = 0; k < 8; k++) {
            float a[8];
            *(float4*)&a[0] = *(const float4*)&As[k][ty];
            *(float4*)&a[4] = *(const float4*)&As[k][ty + 4];
            u64 ap[8];
#pragma unroll
            for (int i = 0; i < 8; i++) ap[i] = pk2(a[i]);
            const u64* b64 = reinterpret_cast<const u64*>(&Bs[k][tx]);
            u64 bp[4];
#pragma unroll
            for (int j = 0; j < 4; j++) bp[j] = b64[j];
#pragma unroll
            for (int i = 0; i < 8; i++)
#pragma unroll
                for (int j = 0; j < 4; j++) fma2(acc2[i][j], ap[i], bp[j]);
        }
    }
#pragma unroll
    for (int i = 0; i < 8; i++) {
        const int mo = (bm + ty + i) * 256 + bn + tx;
#pragma unroll
        for (int j = 0; j < 4; j += 2) {
            float2 p0 = up2(acc2[i][j]), p1 = up2(acc2[i][j + 1]);
            float4 xv = *reinterpret_cast<const float4*>(&Xadd[mo + 2 * j]);
            float4 o;
            o.x = p0.x + xv.x + bias[bn + tx + 2 * j + 0];
            o.y = p0.y + xv.y + bias[bn + tx + 2 * j + 1];
            o.z = p1.x + xv.z + bias[bn + tx + 2 * j + 2];
            o.w = p1.y + xv.w + bias[bn + tx + 2 * j + 3];
            *reinterpret_cast<float4*>(&C[mo + 2 * j]) = o;
        }
    }
}

// ---------------- conv1d GEMM fp32 (duration path — exact), 128x128 tile ---
__global__ __launch_bounds__(256) void conv_gemm(
    const float* __restrict__ A, const float* __restrict__ Wt,
    const float* __restrict__ bias, float* __restrict__ C)
{
    __shared__ float As[8][128];
    __shared__ float Bs[8][128];
    const int bm = blockIdx.x * 128, bn = blockIdx.y * 128;
    const int tid  = threadIdx.x;
    const int arow = tid >> 1,  acol = (tid & 1) << 2;
    const int brow = tid >> 5,  bcol = (tid & 31) << 2;
    const int ty = (tid >> 4) << 3, tx = (tid & 15) << 3;
    const int m = bm + arow;
    const int bb = m >> 10, s = m & 1023;
    const float* Abase = A + (bb << 10) * D;
    u64 acc2[8][4] = {};
    for (int k0 = 0; k0 < KKC; k0 += 8) {
        const int tap = k0 >> 8;
        const int sr  = s + tap - 1;
        const int c0  = (k0 & 255) + acol;
        float4 av = make_float4(0.f, 0.f, 0.f, 0.f);
        if ((unsigned)sr < 1024u)
            av = *reinterpret_cast<const float4*>(Abase + sr * D + c0);
        float4 bv = *reinterpret_cast<const float4*>(&Wt[(k0 + brow) * F + bn + bcol]);
        __syncthreads();
        As[acol + 0][arow] = av.x; As[acol + 1][arow] = av.y;
        As[acol + 2][arow] = av.z; As[acol + 3][arow] = av.w;
        *reinterpret_cast<float4*>(&Bs[brow][bcol]) = bv;
        __syncthreads();
#pragma unroll
        for (int k = 0; k < 8; k++) {
            float a[8];
            *(float4*)&a[0] = *(const float4*)&As[k][ty];
            *(float4*)&a[4] = *(const float4*)&As[k][ty + 4];
            u64 ap[8];
#pragma unroll
            for (int i = 0; i < 8; i++) ap[i] = pk2(a[i]);
            const u64* b64 = reinterpret_cast<const u64*>(&Bs[k][tx]);
            u64 bp[4];
#pragma unroll
            for (int j = 0; j < 4; j++) bp[j] = b64[j];
#pragma unroll
            for (int i = 0; i < 8; i++)
#pragma unroll
                for (int j = 0; j < 4; j++) fma2(acc2[i][j], ap[i], bp[j]);
        }
    }
#pragma unroll
    for (int i = 0; i < 8; i++) {
        const int mo = (bm + ty + i) * F + bn + tx;
#pragma unroll
        for (int j = 0; j < 4; j += 2) {
            float2 p0 = up2(acc2[i][j]), p1 = up2(acc2[i][j + 1]);
            float4 o;
            o.x = fmaxf(p0.x + bias[bn + tx + 2 * j + 0], 0.f);
            o.y = fmaxf(p0.y + bias[bn + tx + 2 * j + 1], 0.f);
            o.z = fmaxf(p1.x + bias[bn + tx + 2 * j + 2], 0.f);
            o.w = fmaxf(p1.y + bias[bn + tx + 2 * j + 3], 0.f);
            *reinterpret_cast<float4*>(&C[mo + 2 * j]) = o;
        }
    }
}

// ---------------- conv1d GEMM via mma.sync tf32 (pitch/energy) -------------
// R10-proven config: 128 threads, 4 warps (2x2) at 64x64, BK=32 double buffer.
#define CCH      24
#define ASTRIDE  36
#define ATILE_B  (128 * ASTRIDE * 4)
#define STG_B    (2 * ATILE_B)
#define CM_SMEM  (2 * STG_B)               // 73728

__global__ __launch_bounds__(128) void conv_mma(
    const float* __restrict__ in0, const float* __restrict__ w0,
    const float* __restrict__ b0p, float* __restrict__ out0,
    const float* __restrict__ in1, const float* __restrict__ w1,
    const float* __restrict__ b1p, float* __restrict__ out1)
{
    extern __shared__ float smf[];
    const float* in  = (blockIdx.z == 0) ? in0 : in1;
    const float* wB  = (blockIdx.z == 0) ? w0  : w1;
    const float* bia = (blockIdx.z == 0) ? b0p : b1p;
    float* out       = (blockIdx.z == 0) ? out0 : out1;

    const int tid = threadIdx.x, lane = tid & 31, wid = tid >> 5;
    const int wm = wid >> 1, wn = wid & 1;
    const int g = lane >> 2, t = lane & 3;

    const int bm = blockIdx.x * 128, bn = blockIdx.y * 128;
    const int bb = bm >> 10, s0 = bm & 1023;
    const float* Abase = in + (bb << 10) * D;

    const uint32_t sbase = smem_u32(smf);
    float acc[4][8][4] = {};

    auto fill = [&](int ch, int st) {
        const int tap = ch >> 3;
        const int c0  = (ch & 7) * 32;
        const uint32_t aS = sbase + st * STG_B;
        const uint32_t bS = aS + ATILE_B;
#pragma unroll
        for (int i = 0; i < 8; i++) {
            int idx = i * 128 + tid;
            int r = idx >> 3, j = idx & 7;
            int sr = s0 + r + tap - 1;
            uint32_t ok = ((unsigned)sr < 1024u) ? 16u : 0u;
            const float* gp = Abase + (ok ? sr : 0) * D + c0 + j * 4;
            cp_async16(aS + (uint32_t)(r * ASTRIDE + j * 4) * 4, gp, ok);
        }
#pragma unroll
        for (int i = 0; i < 8; i++) {
            int idx = i * 128 + tid;
            int r = idx >> 3, j = idx & 7;
            const float* gp = wB + (bn + r) * KKC + tap * 256 + c0 + j * 4;
            cp_async16(bS + (uint32_t)(r * ASTRIDE + j * 4) * 4, gp, 16u);
        }
    };

    fill(0, 0);
    CP_COMMIT();

    for (int ch = 0; ch < CCH; ch++) {
        __syncthreads();
        if (ch + 1 < CCH) {
            fill(ch + 1, (ch + 1) & 1);
            CP_COMMIT();
            CP_WAIT1();
        } else {
            CP_WAIT0();
        }
        __syncthreads();

        const uint32_t aS = sbase + (ch & 1) * STG_B;
        const uint32_t bS = aS + ATILE_B;
#pragma unroll
        for (int ks = 0; ks < 4; ks++) {
            const int kb = ks * 8;
            uint32_t afr[4][4], bfr[8][2];
#pragma unroll
            for (int mt = 0; mt < 4; mt++) {
                uint32_t ab = aS + (uint32_t)((wm * 64 + mt * 16 + g) * ASTRIDE + kb + t) * 4;
                afr[mt][0] = lds32(ab);
                afr[mt][1] = lds32(ab + 8 * ASTRIDE * 4);
                afr[mt][2] = lds32(ab + 16);
                afr[mt][3] = lds32(ab + 8 * ASTRIDE * 4 + 16);
            }
#pragma unroll
            for (int nt = 0; nt < 8; nt++) {
                uint32_t bb2 = bS + (uint32_t)((wn * 64 + nt * 8 + g) * ASTRIDE + kb + t) * 4;
                bfr[nt][0] = lds32(bb2);
                bfr[nt][1] = lds32(bb2 + 16);
            }
#pragma unroll
            for (int mt = 0; mt < 4; mt++)
#pragma unroll
                for (int nt = 0; nt < 8; nt++)
                    mma_tf32(acc[mt][nt], afr[mt], bfr[nt]);
        }
    }

#pragma unroll
    for (int nt = 0; nt < 8; nt++) {
        const int col = bn + wn * 64 + nt * 8 + 2 * t;
        const float bv0 = bia[col], bv1 = bia[col + 1];
#pragma unroll
        for (int mt = 0; mt < 4; mt++) {
            const int row0 = bm + wm * 64 + mt * 16 + g;
            float2 v0, v1;
            v0.x = fmaxf(acc[mt][nt][0] + bv0, 0.f);
            v0.y = fmaxf(acc[mt][nt][1] + bv1, 0.f);
            v1.x = fmaxf(acc[mt][nt][2] + bv0, 0.f);
            v1.y = fmaxf(acc[mt][nt][3] + bv1, 0.f);
            *reinterpret_cast<float2*>(out + row0 * F + col) = v0;
            *reinterpret_cast<float2*>(out + (row0 + 8) * F + col) = v1;
        }
    }
}

// ---------------- layernorm + row norms + fused global reductions ----------
__global__ void ln_norm_k(const float* __restrict__ xp, const float* __restrict__ g,
                          const float* __restrict__ bta, float* __restrict__ xn,
                          float* __restrict__ nxn, float* __restrict__ nxp,
                          unsigned* __restrict__ red)
{
    int row  = blockIdx.x * 8 + (threadIdx.x >> 5);
    int lane = threadIdx.x & 31;
    const float* xr = xp + row * D;
    float v[8], s = 0.f;
#pragma unroll
    for (int i = 0; i < 8; i++) { v[i] = xr[lane + 32 * i]; s += v[i]; }
#pragma unroll
    for (int o = 16; o > 0; o >>= 1) s += __shfl_xor_sync(0xffffffffu, s, o);
    float mean = s * (1.f / 256.f);
    float sq = 0.f, sp = 0.f;
#pragma unroll
    for (int i = 0; i < 8; i++) { float d = v[i] - mean; sq += d * d; sp += v[i] * v[i]; }
#pragma unroll
    for (int o = 16; o > 0; o >>= 1) {
        sq += __shfl_xor_sync(0xffffffffu, sq, o);
        sp += __shfl_xor_sync(0xffffffffu, sp, o);
    }
    float r = 1.0f / sqrtf(sq * (1.f / 256.f) + 1e-5f);
    float n2 = 0.f;
#pragma unroll
    for (int i = 0; i < 8; i++) {
        float y = g[lane + 32 * i] * (v[i] - mean) * r + bta[lane + 32 * i];
        xn[row * D + lane + 32 * i] = y;
        n2 += y * y;
    }
#pragma unroll
    for (int o = 16; o > 0; o >>= 1) n2 += __shfl_xor_sync(0xffffffffu, n2, o);
    __shared__ float rn[8], rp[8];
    float vn = sqrtf(n2), vp = sqrtf(sp);
    if (lane == 0) {
        nxn[row] = vn; nxp[row] = vp;
        rn[threadIdx.x >> 5] = vn; rp[threadIdx.x >> 5] = vp;
    }
    __syncthreads();
    if (threadIdx.x == 0) {
        float m1 = rn[0], mn2 = rp[0], m2 = rp[0];
#pragma unroll
        for (int i = 1; i < 8; i++) {
            m1 = fmaxf(m1, rn[i]);
            mn2 = fminf(mn2, rp[i]); m2 = fmaxf(m2, rp[i]);
        }
        atomicMax(&red[0], __float_as_uint(m1));
        atomicMin(&red[1], __float_as_uint(mn2));
        atomicMax(&red[2], __float_as_uint(m2));
    }
}

// ---------------- heads ----------------------------------------------------
__global__ void dp_final(const float* __restrict__ h2, const float* __restrict__ wl,
                         const float* __restrict__ blp, const float* __restrict__ nxn,
                         const unsigned* __restrict__ red, float* __restrict__ o_ld,
                         float* __restrict__ o_du, int* __restrict__ dint)
{
    int row  = blockIdx.x * 8 + (threadIdx.x >> 5);
    int lane = threadIdx.x & 31;
    const float* hr = h2 + row * F;
    float dot = 0.f;
#pragma unroll
    for (int i = 0; i < 8; i++) dot += hr[lane + 32 * i] * wl[lane + 32 * i];
#pragma unroll
    for (int o = 16; o > 0; o >>= 1) dot += __shfl_xor_sync(0xffffffffu, dot, o);
    if (lane == 0) {
        float base = dot + blp[0];
        float es = 0.8f + 0.4f * (nxn[row] / __uint_as_float(red[0]));
        int s = row & 1023;
        float ps = 1.0f + 0.1f * ((float)s / 1024.0f);
        float ld = (base * es) * ps;
        o_ld[row] = ld;
        float dur = expf(ld);
        o_du[row] = dur;
        dint[row] = (int)rintf(dur);
    }
}

__global__ void pp_final(const float* __restrict__ h2, const float* __restrict__ wl,
                         const float* __restrict__ blp, const float* __restrict__ nxp,
                         const unsigned* __restrict__ red, float* __restrict__ o)
{
    int row  = blockIdx.x * 8 + (threadIdx.x >> 5);
    int lane = threadIdx.x & 31;
    const float* hr = h2 + row * F;
    float d0 = 0.f, d1 = 0.f, d2 = 0.f;
#pragma unroll
    for (int i = 0; i < 8; i++) {
        float h = hr[lane + 32 * i];
        const float* w = wl + (lane + 32 * i) * 3;
        d0 += h * w[0]; d1 += h * w[1]; d2 += h * w[2];
    }
#pragma unroll
    for (int o2 = 16; o2 > 0; o2 >>= 1) {
        d0 += __shfl_xor_sync(0xffffffffu, d0, o2);
        d1 += __shfl_xor_sync(0xffffffffu, d1, o2);
        d2 += __shfl_xor_sync(0xffffffffu, d2, o2);
    }
    if (lane == 0) {
        float p0 = d0 + blp[0], p1 = d1 + blp[1], p2 = d2 + blp[2];
        float mn = __uint_as_float(red[1]), mx = __uint_as_float(red[2]);
        float en = (nxp[row] - mn) / (mx - mn + 1e-8f);
        float f0s = 100.f + 400.f * en;
        float f0b = expf(p0) * f0s / 220.f;
        o[row * 3 + 0] = logf(f0b + 1e-8f);
        o[row * 3 + 1] = p1;
        o[row * 3 + 2] = p2;
    }
}

__global__ void ep_final(const float* __restrict__ h2, const float* __restrict__ wl,
                         const float* __restrict__ blp, float* __restrict__ o)
{
    int row  = blockIdx.x * 8 + (threadIdx.x >> 5);
    int lane = threadIdx.x & 31;
    const float* hr = h2 + row * F;
    float dot = 0.f;
#pragma unroll
    for (int i = 0; i < 8; i++) dot += hr[lane + 32 * i] * wl[lane + 32 * i];
#pragma unroll
    for (int o2 = 16; o2 > 0; o2 >>= 1) dot += __shfl_xor_sync(0xffffffffu, dot, o2);
    if (lane == 0) o[row] = dot + blp[0];
}

// ---------------- per-batch inclusive scan + clip (warp scan) --------------
__global__ void cumsum_k(const int* __restrict__ dint, int* __restrict__ cumc) {
    int b = blockIdx.x, t = threadIdx.x;
    int lane = t & 31, w = t >> 5;
    int s = dint[b * 1024 + t];
#pragma unroll
    for (int o = 1; o < 32; o <<= 1) {
        int u = __shfl_up_sync(0xffffffffu, s, o);
        if (lane >= o) s += u;
    }
    __shared__ int ws[32];
    if (lane == 31) ws[w] = s;
    __syncthreads();
    if (w == 0) {
        int x = ws[lane];
#pragma unroll
        for (int o = 1; o < 32; o <<= 1) {
            int u = __shfl_up_sync(0xffffffffu, x, o);
            if (lane >= o) x += u;
        }
        ws[lane] = x;
    }
    __syncthreads();
    int base = (w > 0) ? ws[w - 1] : 0;
    cumc[b * 1024 + t] = min(s + base, TMAX);
}

// ---------------- length regulation ----------------------------------------
__global__ __launch_bounds__(256) void expand_k(
    const float* __restrict__ xp, const int* __restrict__ cumc,
    float* __restrict__ o_exp, float* __restrict__ o_msk)
{
    __shared__ int cs[1024];
    __shared__ int idxs[128];
    int b  = blockIdx.y;
    int t0 = blockIdx.x * 128;
    int tid = threadIdx.x;
    for (int i = tid; i < 1024; i += 256) cs[i] = cumc[b * 1024 + i];
    __syncthreads();
    int cend = cs[1023];
    if (tid < 128) {
        int t = t0 + tid;
        int lo = 0, hi = 1024;
        while (lo < hi) { int mid = (lo + hi) >> 1; if (cs[mid] <= t) lo = mid + 1; else hi = mid; }
        bool mask = (t >= cend);
        idxs[tid] = mask ? -1 : min(lo, 1023);
        o_msk[b * TMAX + t] = mask ? 1.0f : 0.0f;
    }
    __syncthreads();
    const float* xb = xp + (b << 10) * D;
    float* ob = o_exp + ((long long)b * TMAX + t0) * D;
    for (int i = tid; i < 128 * 64; i += 256) {
        int fr = i >> 6, c4 = (i & 63) << 2;
        int id = idxs[fr];
        float4 v = make_float4(0.f, 0.f, 0.f, 0.f);
        if (id >= 0) v = *reinterpret_cast<const float4*>(xb + id * D + c4);
        *reinterpret_cast<float4*>(ob + (long long)fr * D + c4) = v;
    }
}

// ---------------- host orchestration ---------------------------------------
extern "C" void kernel_launch(void* const* d_in, const int* in_sizes, int n_in,
                              void* d_out, int out_size)
{
    const float* x     = (const float*)d_in[0];
    const float* nph   = (const float*)d_in[2];
    const float* ln_g  = (const float*)d_in[3];
    const float* ln_b  = (const float*)d_in[4];
    const float* dp_w1 = (const float*)d_in[5];  const float* dp_b1 = (const float*)d_in[6];
    const float* dp_w2 = (const float*)d_in[7];  const float* dp_b2 = (const float*)d_in[8];
    const float* dp_wl = (const float*)d_in[9];  const float* dp_bl = (const float*)d_in[10];
    const float* pp_w1 = (const float*)d_in[11]; const float* pp_b1 = (const float*)d_in[12];
    const float* pp_w2 = (const float*)d_in[13]; const float* pp_b2 = (const float*)d_in[14];
    const float* pp_wl = (const float*)d_in[15]; const float* pp_bl = (const float*)d_in[16];
    const float* ep_w1 = (const float*)d_in[17]; const float* ep_b1 = (const float*)d_in[18];
    const float* ep_w2 = (const float*)d_in[19]; const float* ep_b2 = (const float*)d_in[20];
    const float* ep_wl = (const float*)d_in[21]; const float* ep_bl = (const float*)d_in[22];
    const float* np_w  = (const float*)d_in[23]; const float* np_b  = (const float*)d_in[24];

    float* out  = (float*)d_out;
    float* o_ld = out;
    float* o_du = out + R;
    float* o_pp = out + 2 * R;
    float* o_en = out + 5 * R;
    float* o_ex = out + 6 * R;
    float* o_mk = out + 6 * R + (long long)NB * TMAX * D;

    float *xp, *xn, *h1, *h2, *h3, *h4, *h5, *h6, *wt, *nxn, *nxp;
    unsigned* red; int *dint, *cumc;
    cudaGetSymbolAddress((void**)&xp,   g_xp);
    cudaGetSymbolAddress((void**)&xn,   g_xn);
    cudaGetSymbolAddress((void**)&h1,   g_h1);
    cudaGetSymbolAddress((void**)&h2,   g_h2);
    cudaGetSymbolAddress((void**)&h3,   g_h3);
    cudaGetSymbolAddress((void**)&h4,   g_h4);
    cudaGetSymbolAddress((void**)&h5,   g_h5);
    cudaGetSymbolAddress((void**)&h6,   g_h6);
    cudaGetSymbolAddress((void**)&wt,   g_wt);
    cudaGetSymbolAddress((void**)&nxn,  g_nxn);
    cudaGetSymbolAddress((void**)&nxp,  g_nxp);
    cudaGetSymbolAddress((void**)&red,  g_red);
    cudaGetSymbolAddress((void**)&dint, g_dint);
    cudaGetSymbolAddress((void**)&cumc, g_cumc);

    cudaFuncSetAttribute(conv_mma, cudaFuncAttributeMaxDynamicSharedMemorySize, CM_SMEM);

    const int WSL = KKC * F;

    // ---- main: init, then legal fork for side stream ----
    init_red<<<1, 32>>>(red);
    cudaEventRecord(g_ss.ev0, 0);
    cudaStreamWaitEvent(g_ss.s1, g_ss.ev0, 0);

    // ---- side (LOW priority): weight transpose (overlaps gemm_np) ----
    transpose_all<<<dim3((KKC * F + 255) / 256, 6), 256, 0, g_ss.s1>>>(
        dp_w1, dp_w2, pp_w1, pp_w2, ep_w1, ep_w2, wt);
    cudaEventRecord(g_ss.evW, g_ss.s1);

    // ---- main: note projection ----
    gemm_np<<<dim3(R / 128, 2), 256>>>(nph, np_w, np_b, x, xp);
    cudaEventRecord(g_ss.evF, 0);

    // ---- side (LOW priority): tensor branch (needs xp + wt) ----
    cudaStreamWaitEvent(g_ss.s1, g_ss.evF, 0);
    dim3 gm(R / 128, 2, 2);
    conv_mma<<<gm, 128, CM_SMEM, g_ss.s1>>>(
        xp, wt + 2 * WSL, pp_b1, h1,
        xp, wt + 4 * WSL, ep_b1, h3);
    conv_mma<<<gm, 128, CM_SMEM, g_ss.s1>>>(
        h1, wt + 3 * WSL, pp_b2, h2,
        h3, wt + 5 * WSL, ep_b2, h4);

    // ---- main: layernorm (overlaps conv_mma layer 1) ----
    ln_norm_k<<<R / 8, 256>>>(xp, ln_g, ln_b, xn, nxn, nxp, red);
    cudaEventRecord(g_ss.evL, 0);

    // side finals need red/nxp from ln_norm
    cudaStreamWaitEvent(g_ss.s1, g_ss.evL, 0);
    pp_final<<<R / 8, 256, 0, g_ss.s1>>>(h2, pp_wl, pp_bl, nxp, red, o_pp);
    ep_final<<<R / 8, 256, 0, g_ss.s1>>>(h4, ep_wl, ep_bl, o_en);
    cudaEventRecord(g_ss.evJ, g_ss.s1);

    // ---- main (HIGH priority, critical path): duration chain ----
    cudaStreamWaitEvent(0, g_ss.evW, 0);
    dim3 gg(R / 128, 2);
    conv_gemm<<<gg, 256>>>(xn, wt + 0 * WSL, dp_b1, h5);
    conv_gemm<<<gg, 256>>>(h5, wt + 1 * WSL, dp_b2, h6);
    dp_final<<<R / 8, 256>>>(h6, dp_wl, dp_bl, nxn, red, o_ld, o_du, dint);
    cumsum_k<<<NB, 1024>>>(dint, cumc);
    expand_k<<<dim3(TMAX / 128, NB), 256>>>(xp, cumc, o_ex, o_mk);

    // ---- join ----
    cudaStreamWaitEvent(0, g_ss.evJ, 0);
}

// round 17
// speedup vs baseline: 1.0148x; 1.0022x over previous
#include <cuda_runtime.h>
#include <math.h>
#include <stdint.h>

#define R    16384      // B*S rows
#define D    256
#define F    256
#define NB   16
#define TMAX 8192
#define KKC  768        // 3 * 256 im2col K

typedef unsigned long long u64;

// ---------------- scratch (static device allocations only) ----------------
__device__ float g_xp[R * D];
__device__ float g_xn[R * D];
__device__ float g_h1[R * F];
__device__ float g_h2[R * F];
__device__ float g_h3[R * F];
__device__ float g_h4[R * F];
__device__ float g_h5[R * F];
__device__ float g_h6[R * F];
__device__ float g_wt[6 * KKC * F];
__device__ float g_nxn[R];
__device__ float g_nxp[R];
__device__ unsigned g_red[3];
__device__ int   g_dint[R];
__device__ int   g_cumc[R];

// ---------------- host-side stream/event resources (created pre-run) -------
struct SideStream {
    cudaStream_t s1;
    cudaEvent_t ev0, evF, evJ, evW, evL;
    SideStream() {
        int leastP = 0, greatestP = 0;
        cudaDeviceGetStreamPriorityRange(&leastP, &greatestP);
        cudaStreamCreateWithPriority(&s1, cudaStreamNonBlocking, leastP);
        cudaEventCreateWithFlags(&ev0, cudaEventDisableTiming);
        cudaEventCreateWithFlags(&evF, cudaEventDisableTiming);
        cudaEventCreateWithFlags(&evJ, cudaEventDisableTiming);
        cudaEventCreateWithFlags(&evW, cudaEventDisableTiming);
        cudaEventCreateWithFlags(&evL, cudaEventDisableTiming);
    }
};
static SideStream g_ss;

// =================== portable PTX helpers ==================================
__device__ __forceinline__ uint32_t smem_u32(const void* p) {
    uint32_t a;
    asm("{ .reg .u64 t; cvta.to.shared.u64 t, %1; cvt.u32.u64 %0, t; }" : "=r"(a) : "l"(p));
    return a;
}
__device__ __forceinline__ void cp_async16(uint32_t dst, const void* src, uint32_t srcsize) {
    asm volatile("cp.async.cg.shared.global [%0], [%1], 16, %2;"
                 :: "r"(dst), "l"(src), "r"(srcsize) : "memory");
}
#define CP_COMMIT() asm volatile("cp.async.commit_group;" ::: "memory")
#define CP_WAIT1()  asm volatile("cp.async.wait_group 1;" ::: "memory")
#define CP_WAIT0()  asm volatile("cp.async.wait_group 0;" ::: "memory")
__device__ __forceinline__ uint32_t lds32(uint32_t addr) {
    uint32_t v;
    asm volatile("ld.shared.b32 %0, [%1];" : "=r"(v) : "r"(addr));
    return v;
}
__device__ __forceinline__ void mma_tf32(float* c, const uint32_t* a, const uint32_t* b) {
    asm volatile("mma.sync.aligned.m16n8k8.row.col.f32.tf32.tf32.f32 "
                 "{%0,%1,%2,%3}, {%4,%5,%6,%7}, {%8,%9}, {%0,%1,%2,%3};"
                 : "+f"(c[0]), "+f"(c[1]), "+f"(c[2]), "+f"(c[3])
                 : "r"(a[0]), "r"(a[1]), "r"(a[2]), "r"(a[3]), "r"(b[0]), "r"(b[1]));
}
// ---- packed fp32x2 FMA (harmless if lowered to 2x FFMA) -------------------
__device__ __forceinline__ u64 pk2(float x) {
    u64 r; uint32_t xi = __float_as_uint(x);
    asm("mov.b64 %0, {%1, %1};" : "=l"(r) : "r"(xi));
    return r;
}
__device__ __forceinline__ void fma2(u64& acc, u64 a, u64 b) {
    asm("fma.rn.f32x2 %0, %1, %2, %0;" : "+l"(acc) : "l"(a), "l"(b));
}
__device__ __forceinline__ float2 up2(u64 v) {
    float2 f; uint32_t lo, hi;
    asm("mov.b64 {%0, %1}, %2;" : "=r"(lo), "=r"(hi) : "l"(v));
    f.x = __uint_as_float(lo); f.y = __uint_as_float(hi);
    return f;
}

// ---------------- init global reduction cells ------------------------------
__global__ void init_red(unsigned* red) {
    if (threadIdx.x == 0) { red[0] = 0u; red[1] = 0x7F800000u; red[2] = 0u; }
}

// ---------------- fused weight transpose -----------------------------------
__global__ void transpose_all(const float* __restrict__ dp1, const float* __restrict__ dp2,
                              const float* __restrict__ pp1, const float* __restrict__ pp2,
                              const float* __restrict__ ep1, const float* __restrict__ ep2,
                              float* __restrict__ wt)
{
    int y = blockIdx.y;
    const float* src = (y == 0) ? dp1 : (y == 1) ? dp2 : (y == 2) ? pp1 : (y == 3) ? pp2 : (y == 4) ? ep1 : ep2;
    float* dst = wt + y * (KKC * F);
    int idx = blockIdx.x * 256 + threadIdx.x;
    if (idx >= KKC * F) return;
    if (y < 2) {
        int f = idx & 255, kc = idx >> 8;
        int k = kc >> 8, c = kc & 255;
        dst[idx] = src[(f * 256 + c) * 3 + k];
    } else {
        int f = idx / KKC, kk = idx - f * KKC;
        int k = kk >> 8, c = kk & 255;
        dst[idx] = src[(f * 256 + c) * 3 + k];
    }
}

// ---------------- note-projection GEMM (fp32, exact) -----------------------
__global__ __launch_bounds__(256) void gemm_np(
    const float* __restrict__ A, const float* __restrict__ W,
    const float* __restrict__ bias, const float* __restrict__ Xadd,
    float* __restrict__ C)
{
    __shared__ float As[8][128];
    __shared__ float Bs[8][128];
    const int bm = blockIdx.x * 128, bn = blockIdx.y * 128;
    const int tid  = threadIdx.x;
    const int arow = tid >> 1,  acol = (tid & 1) << 2;
    const int brow = tid >> 5,  bcol = (tid & 31) << 2;
    const int ty = (tid >> 4) << 3, tx = (tid & 15) << 3;
    u64 acc2[8][4] = {};
    for (int k0 = 0; k0 < 256; k0 += 8) {
        float4 av = *reinterpret_cast<const float4*>(&A[(bm + arow) * 256 + k0 + acol]);
        float4 bv = *reinterpret_cast<const float4*>(&W[(k0 + brow) * 256 + bn + bcol]);
        __syncthreads();
        As[acol + 0][arow] = av.x; As[acol + 1][arow] = av.y;
        As[acol + 2][arow] = av.z; As[acol + 3][arow] = av.w;
        *reinterpret_cast<float4*>(&Bs[brow][bcol]) = bv;
        __syncthreads();
#pragma unroll
        for (int k = 0; k < 8; k++) {
            float a[8];
            *(float4*)&a[0] = *(const float4*)&As[k][ty];
            *(float4*)&a[4] = *(const float4*)&As[k][ty + 4];
            u64 ap[8];
#pragma unroll
            for (int i = 0; i < 8; i++) ap[i] = pk2(a[i]);
            const u64* b64 = reinterpret_cast<const u64*>(&Bs[k][tx]);
            u64 bp[4];
#pragma unroll
            for (int j = 0; j < 4; j++) bp[j] = b64[j];
#pragma unroll
            for (int i = 0; i < 8; i++)
#pragma unroll
                for (int j = 0; j < 4; j++) fma2(acc2[i][j], ap[i], bp[j]);
        }
    }
#pragma unroll
    for (int i = 0; i < 8; i++) {
        const int mo = (bm + ty + i) * 256 + bn + tx;
#pragma unroll
        for (int j = 0; j < 4; j += 2) {
            float2 p0 = up2(acc2[i][j]), p1 = up2(acc2[i][j + 1]);
            float4 xv = *reinterpret_cast<const float4*>(&Xadd[mo + 2 * j]);
            float4 o;
            o.x = p0.x + xv.x + bias[bn + tx + 2 * j + 0];
            o.y = p0.y + xv.y + bias[bn + tx + 2 * j + 1];
            o.z = p1.x + xv.z + bias[bn + tx + 2 * j + 2];
            o.w = p1.y + xv.w + bias[bn + tx + 2 * j + 3];
            *reinterpret_cast<float4*>(&C[mo + 2 * j]) = o;
        }
    }
}

// ---------------- conv1d GEMM fp32 (duration path — exact), 128x128 tile ---
__global__ __launch_bounds__(256) void conv_gemm(
    const float* __restrict__ A, const float* __restrict__ Wt,
    const float* __restrict__ bias, float* __restrict__ C)
{
    __shared__ float As[8][128];
    __shared__ float Bs[8][128];
    const int bm = blockIdx.x * 128, bn = blockIdx.y * 128;
    const int tid  = threadIdx.x;
    const int arow = tid >> 1,  acol = (tid & 1) << 2;
    const int brow = tid >> 5,  bcol = (tid & 31) << 2;
    const int ty = (tid >> 4) << 3, tx = (tid & 15) << 3;
    const int m = bm + arow;
    const int bb = m >> 10, s = m & 1023;
    const float* Abase = A + (bb << 10) * D;
    u64 acc2[8][4] = {};
    for (int k0 = 0; k0 < KKC; k0 += 8) {
        const int tap = k0 >> 8;
        const int sr  = s + tap - 1;
        const int c0  = (k0 & 255) + acol;
        float4 av = make_float4(0.f, 0.f, 0.f, 0.f);
        if ((unsigned)sr < 1024u)
            av = *reinterpret_cast<const float4*>(Abase + sr * D + c0);
        float4 bv = *reinterpret_cast<const float4*>(&Wt[(k0 + brow) * F + bn + bcol]);
        __syncthreads();
        As[acol + 0][arow] = av.x; As[acol + 1][arow] = av.y;
        As[acol + 2][arow] = av.z; As[acol + 3][arow] = av.w;
        *reinterpret_cast<float4*>(&Bs[brow][bcol]) = bv;
        __syncthreads();
#pragma unroll
        for (int k = 0; k < 8; k++) {
            float a[8];
            *(float4*)&a[0] = *(const float4*)&As[k][ty];
            *(float4*)&a[4] = *(const float4*)&As[k][ty + 4];
            u64 ap[8];
#pragma unroll
            for (int i = 0; i < 8; i++) ap[i] = pk2(a[i]);
            const u64* b64 = reinterpret_cast<const u64*>(&Bs[k][tx]);
            u64 bp[4];
#pragma unroll
            for (int j = 0; j < 4; j++) bp[j] = b64[j];
#pragma unroll
            for (int i = 0; i < 8; i++)
#pragma unroll
                for (int j = 0; j < 4; j++) fma2(acc2[i][j], ap[i], bp[j]);
        }
    }
#pragma unroll
    for (int i = 0; i < 8; i++) {
        const int mo = (bm + ty + i) * F + bn + tx;
#pragma unroll
        for (int j = 0; j < 4; j += 2) {
            float2 p0 = up2(acc2[i][j]), p1 = up2(acc2[i][j + 1]);
            float4 o;
            o.x = fmaxf(p0.x + bias[bn + tx + 2 * j + 0], 0.f);
            o.y = fmaxf(p0.y + bias[bn + tx + 2 * j + 1], 0.f);
            o.z = fmaxf(p1.x + bias[bn + tx + 2 * j + 2], 0.f);
            o.w = fmaxf(p1.y + bias[bn + tx + 2 * j + 3], 0.f);
            *reinterpret_cast<float4*>(&C[mo + 2 * j]) = o;
        }
    }
}

// ---------------- conv1d GEMM via mma.sync tf32 (pitch/energy) -------------
// 128 threads, 4 warps (2x2) at 64x64, BK=32 smem double buffer,
// PLUS register double-buffering of fragments across ks steps.
#define CCH      24
#define ASTRIDE  36
#define ATILE_B  (128 * ASTRIDE * 4)
#define STG_B    (2 * ATILE_B)
#define CM_SMEM  (2 * STG_B)               // 73728

__global__ __launch_bounds__(128) void conv_mma(
    const float* __restrict__ in0, const float* __restrict__ w0,
    const float* __restrict__ b0p, float* __restrict__ out0,
    const float* __restrict__ in1, const float* __restrict__ w1,
    const float* __restrict__ b1p, float* __restrict__ out1)
{
    extern __shared__ float smf[];
    const float* in  = (blockIdx.z == 0) ? in0 : in1;
    const float* wB  = (blockIdx.z == 0) ? w0  : w1;
    const float* bia = (blockIdx.z == 0) ? b0p : b1p;
    float* out       = (blockIdx.z == 0) ? out0 : out1;

    const int tid = threadIdx.x, lane = tid & 31, wid = tid >> 5;
    const int wm = wid >> 1, wn = wid & 1;
    const int g = lane >> 2, t = lane & 3;

    const int bm = blockIdx.x * 128, bn = blockIdx.y * 128;
    const int bb = bm >> 10, s0 = bm & 1023;
    const float* Abase = in + (bb << 10) * D;

    const uint32_t sbase = smem_u32(smf);
    float acc[4][8][4] = {};

    auto fill = [&](int ch, int st) {
        const int tap = ch >> 3;
        const int c0  = (ch & 7) * 32;
        const uint32_t aS = sbase + st * STG_B;
        const uint32_t bS = aS + ATILE_B;
#pragma unroll
        for (int i = 0; i < 8; i++) {
            int idx = i * 128 + tid;
            int r = idx >> 3, j = idx & 7;
            int sr = s0 + r + tap - 1;
            uint32_t ok = ((unsigned)sr < 1024u) ? 16u : 0u;
            const float* gp = Abase + (ok ? sr : 0) * D + c0 + j * 4;
            cp_async16(aS + (uint32_t)(r * ASTRIDE + j * 4) * 4, gp, ok);
        }
#pragma unroll
        for (int i = 0; i < 8; i++) {
            int idx = i * 128 + tid;
            int r = idx >> 3, j = idx & 7;
            const float* gp = wB + (bn + r) * KKC + tap * 256 + c0 + j * 4;
            cp_async16(bS + (uint32_t)(r * ASTRIDE + j * 4) * 4, gp, 16u);
        }
    };

    // per-ks fragment loader into caller-provided register buffers
    auto load_frags = [&](uint32_t aS, uint32_t bS, int ks,
                          uint32_t afr[4][4], uint32_t bfr[8][2]) {
        const int kb = ks * 8;
#pragma unroll
        for (int mt = 0; mt < 4; mt++) {
            uint32_t ab = aS + (uint32_t)((wm * 64 + mt * 16 + g) * ASTRIDE + kb + t) * 4;
            afr[mt][0] = lds32(ab);
            afr[mt][1] = lds32(ab + 8 * ASTRIDE * 4);
            afr[mt][2] = lds32(ab + 16);
            afr[mt][3] = lds32(ab + 8 * ASTRIDE * 4 + 16);
        }
#pragma unroll
        for (int nt = 0; nt < 8; nt++) {
            uint32_t bb2 = bS + (uint32_t)((wn * 64 + nt * 8 + g) * ASTRIDE + kb + t) * 4;
            bfr[nt][0] = lds32(bb2);
            bfr[nt][1] = lds32(bb2 + 16);
        }
    };

    fill(0, 0);
    CP_COMMIT();

    uint32_t afr[2][4][4], bfr[2][8][2];

    for (int ch = 0; ch < CCH; ch++) {
        __syncthreads();
        if (ch + 1 < CCH) {
            fill(ch + 1, (ch + 1) & 1);
            CP_COMMIT();
            CP_WAIT1();
        } else {
            CP_WAIT0();
        }
        __syncthreads();

        const uint32_t aS = sbase + (ch & 1) * STG_B;
        const uint32_t bS = aS + ATILE_B;

        // software pipeline: load frags(ks+1) while issuing mma(ks)
        load_frags(aS, bS, 0, afr[0], bfr[0]);
#pragma unroll
        for (int ks = 0; ks < 4; ks++) {
            const int cur = ks & 1, nxt = cur ^ 1;
            if (ks + 1 < 4)
                load_frags(aS, bS, ks + 1, afr[nxt], bfr[nxt]);
#pragma unroll
            for (int mt = 0; mt < 4; mt++)
#pragma unroll
                for (int nt = 0; nt < 8; nt++)
                    mma_tf32(acc[mt][nt], afr[cur][mt], bfr[cur][nt]);
        }
    }

#pragma unroll
    for (int nt = 0; nt < 8; nt++) {
        const int col = bn + wn * 64 + nt * 8 + 2 * t;
        const float bv0 = bia[col], bv1 = bia[col + 1];
#pragma unroll
        for (int mt = 0; mt < 4; mt++) {
            const int row0 = bm + wm * 64 + mt * 16 + g;
            float2 v0, v1;
            v0.x = fmaxf(acc[mt][nt][0] + bv0, 0.f);
            v0.y = fmaxf(acc[mt][nt][1] + bv1, 0.f);
            v1.x = fmaxf(acc[mt][nt][2] + bv0, 0.f);
            v1.y = fmaxf(acc[mt][nt][3] + bv1, 0.f);
            *reinterpret_cast<float2*>(out + row0 * F + col) = v0;
            *reinterpret_cast<float2*>(out + (row0 + 8) * F + col) = v1;
        }
    }
}

// ---------------- layernorm + row norms + fused global reductions ----------
__global__ void ln_norm_k(const float* __restrict__ xp, const float* __restrict__ g,
                          const float* __restrict__ bta, float* __restrict__ xn,
                          float* __restrict__ nxn, float* __restrict__ nxp,
                          unsigned* __restrict__ red)
{
    int row  = blockIdx.x * 8 + (threadIdx.x >> 5);
    int lane = threadIdx.x & 31;
    const float* xr = xp + row * D;
    float v[8], s = 0.f;
#pragma unroll
    for (int i = 0; i < 8; i++) { v[i] = xr[lane + 32 * i]; s += v[i]; }
#pragma unroll
    for (int o = 16; o > 0; o >>= 1) s += __shfl_xor_sync(0xffffffffu, s, o);
    float mean = s * (1.f / 256.f);
    float sq = 0.f, sp = 0.f;
#pragma unroll
    for (int i = 0; i < 8; i++) { float d = v[i] - mean; sq += d * d; sp += v[i] * v[i]; }
#pragma unroll
    for (int o = 16; o > 0; o >>= 1) {
        sq += __shfl_xor_sync(0xffffffffu, sq, o);
        sp += __shfl_xor_sync(0xffffffffu, sp, o);
    }
    float r = 1.0f / sqrtf(sq * (1.f / 256.f) + 1e-5f);
    float n2 = 0.f;
#pragma unroll
    for (int i = 0; i < 8; i++) {
        float y = g[lane + 32 * i] * (v[i] - mean) * r + bta[lane + 32 * i];
        xn[row * D + lane + 32 * i] = y;
        n2 += y * y;
    }
#pragma unroll
    for (int o = 16; o > 0; o >>= 1) n2 += __shfl_xor_sync(0xffffffffu, n2, o);
    __shared__ float rn[8], rp[8];
    float vn = sqrtf(n2), vp = sqrtf(sp);
    if (lane == 0) {
        nxn[row] = vn; nxp[row] = vp;
        rn[threadIdx.x >> 5] = vn; rp[threadIdx.x >> 5] = vp;
    }
    __syncthreads();
    if (threadIdx.x == 0) {
        float m1 = rn[0], mn2 = rp[0], m2 = rp[0];
#pragma unroll
        for (int i = 1; i < 8; i++) {
            m1 = fmaxf(m1, rn[i]);
            mn2 = fminf(mn2, rp[i]); m2 = fmaxf(m2, rp[i]);
        }
        atomicMax(&red[0], __float_as_uint(m1));
        atomicMin(&red[1], __float_as_uint(mn2));
        atomicMax(&red[2], __float_as_uint(m2));
    }
}

// ---------------- heads ----------------------------------------------------
__global__ void dp_final(const float* __restrict__ h2, const float* __restrict__ wl,
                         const float* __restrict__ blp, const float* __restrict__ nxn,
                         const unsigned* __restrict__ red, float* __restrict__ o_ld,
                         float* __restrict__ o_du, int* __restrict__ dint)
{
    int row  = blockIdx.x * 8 + (threadIdx.x >> 5);
    int lane = threadIdx.x & 31;
    const float* hr = h2 + row * F;
    float dot = 0.f;
#pragma unroll
    for (int i = 0; i < 8; i++) dot += hr[lane + 32 * i] * wl[lane + 32 * i];
#pragma unroll
    for (int o = 16; o > 0; o >>= 1) dot += __shfl_xor_sync(0xffffffffu, dot, o);
    if (lane == 0) {
        float base = dot + blp[0];
        float es = 0.8f + 0.4f * (nxn[row] / __uint_as_float(red[0]));
        int s = row & 1023;
        float ps = 1.0f + 0.1f * ((float)s / 1024.0f);
        float ld = (base * es) * ps;
        o_ld[row] = ld;
        float dur = expf(ld);
        o_du[row] = dur;
        dint[row] = (int)rintf(dur);
    }
}

__global__ void pp_final(const float* __restrict__ h2, const float* __restrict__ wl,
                         const float* __restrict__ blp, const float* __restrict__ nxp,
                         const unsigned* __restrict__ red, float* __restrict__ o)
{
    int row  = blockIdx.x * 8 + (threadIdx.x >> 5);
    int lane = threadIdx.x & 31;
    const float* hr = h2 + row * F;
    float d0 = 0.f, d1 = 0.f, d2 = 0.f;
#pragma unroll
    for (int i = 0; i < 8; i++) {
        float h = hr[lane + 32 * i];
        const float* w = wl + (lane + 32 * i) * 3;
        d0 += h * w[0]; d1 += h * w[1]; d2 += h * w[2];
    }
#pragma unroll
    for (int o2 = 16; o2 > 0; o2 >>= 1) {
        d0 += __shfl_xor_sync(0xffffffffu, d0, o2);
        d1 += __shfl_xor_sync(0xffffffffu, d1, o2);
        d2 += __shfl_xor_sync(0xffffffffu, d2, o2);
    }
    if (lane == 0) {
        float p0 = d0 + blp[0], p1 = d1 + blp[1], p2 = d2 + blp[2];
        float mn = __uint_as_float(red[1]), mx = __uint_as_float(red[2]);
        float en = (nxp[row] - mn) / (mx - mn + 1e-8f);
        float f0s = 100.f + 400.f * en;
        float f0b = expf(p0) * f0s / 220.f;
        o[row * 3 + 0] = logf(f0b + 1e-8f);
        o[row * 3 + 1] = p1;
        o[row * 3 + 2] = p2;
    }
}

__global__ void ep_final(const float* __restrict__ h2, const float* __restrict__ wl,
                         const float* __restrict__ blp, float* __restrict__ o)
{
    int row  = blockIdx.x * 8 + (threadIdx.x >> 5);
    int lane = threadIdx.x & 31;
    const float* hr = h2 + row * F;
    float dot = 0.f;
#pragma unroll
    for (int i = 0; i < 8; i++) dot += hr[lane + 32 * i] * wl[lane + 32 * i];
#pragma unroll
    for (int o2 = 16; o2 > 0; o2 >>= 1) dot += __shfl_xor_sync(0xffffffffu, dot, o2);
    if (lane == 0) o[row] = dot + blp[0];
}

// ---------------- per-batch inclusive scan + clip (warp scan) --------------
__global__ void cumsum_k(const int* __restrict__ dint, int* __restrict__ cumc) {
    int b = blockIdx.x, t = threadIdx.x;
    int lane = t & 31, w = t >> 5;
    int s = dint[b * 1024 + t];
#pragma unroll
    for (int o = 1; o < 32; o <<= 1) {
        int u = __shfl_up_sync(0xffffffffu, s, o);
        if (lane >= o) s += u;
    }
    __shared__ int ws[32];
    if (lane == 31) ws[w] = s;
    __syncthreads();
    if (w == 0) {
        int x = ws[lane];
#pragma unroll
        for (int o = 1; o < 32; o <<= 1) {
            int u = __shfl_up_sync(0xffffffffu, x, o);
            if (lane >= o) x += u;
        }
        ws[lane] = x;
    }
    __syncthreads();
    int base = (w > 0) ? ws[w - 1] : 0;
    cumc[b * 1024 + t] = min(s + base, TMAX);
}

// ---------------- length regulation ----------------------------------------
__global__ __launch_bounds__(256) void expand_k(
    const float* __restrict__ xp, const int* __restrict__ cumc,
    float* __restrict__ o_exp, float* __restrict__ o_msk)
{
    __shared__ int cs[1024];
    __shared__ int idxs[128];
    int b  = blockIdx.y;
    int t0 = blockIdx.x * 128;
    int tid = threadIdx.x;
    for (int i = tid; i < 1024; i += 256) cs[i] = cumc[b * 1024 + i];
    __syncthreads();
    int cend = cs[1023];
    if (tid < 128) {
        int t = t0 + tid;
        int lo = 0, hi = 1024;
        while (lo < hi) { int mid = (lo + hi) >> 1; if (cs[mid] <= t) lo = mid + 1; else hi = mid; }
        bool mask = (t >= cend);
        idxs[tid] = mask ? -1 : min(lo, 1023);
        o_msk[b * TMAX + t] = mask ? 1.0f : 0.0f;
    }
    __syncthreads();
    const float* xb = xp + (b << 10) * D;
    float* ob = o_exp + ((long long)b * TMAX + t0) * D;
    for (int i = tid; i < 128 * 64; i += 256) {
        int fr = i >> 6, c4 = (i & 63) << 2;
        int id = idxs[fr];
        float4 v = make_float4(0.f, 0.f, 0.f, 0.f);
        if (id >= 0) v = *reinterpret_cast<const float4*>(xb + id * D + c4);
        *reinterpret_cast<float4*>(ob + (long long)fr * D + c4) = v;
    }
}

// ---------------- host orchestration ---------------------------------------
extern "C" void kernel_launch(void* const* d_in, const int* in_sizes, int n_in,
                              void* d_out, int out_size)
{
    const float* x     = (const float*)d_in[0];
    const float* nph   = (const float*)d_in[2];
    const float* ln_g  = (const float*)d_in[3];
    const float* ln_b  = (const float*)d_in[4];
    const float* dp_w1 = (const float*)d_in[5];  const float* dp_b1 = (const float*)d_in[6];
    const float* dp_w2 = (const float*)d_in[7];  const float* dp_b2 = (const float*)d_in[8];
    const float* dp_wl = (const float*)d_in[9];  const float* dp_bl = (const float*)d_in[10];
    const float* pp_w1 = (const float*)d_in[11]; const float* pp_b1 = (const float*)d_in[12];
    const float* pp_w2 = (const float*)d_in[13]; const float* pp_b2 = (const float*)d_in[14];
    const float* pp_wl = (const float*)d_in[15]; const float* pp_bl = (const float*)d_in[16];
    const float* ep_w1 = (const float*)d_in[17]; const float* ep_b1 = (const float*)d_in[18];
    const float* ep_w2 = (const float*)d_in[19]; const float* ep_b2 = (const float*)d_in[20];
    const float* ep_wl = (const float*)d_in[21]; const float* ep_bl = (const float*)d_in[22];
    const float* np_w  = (const float*)d_in[23]; const float* np_b  = (const float*)d_in[24];

    float* out  = (float*)d_out;
    float* o_ld = out;
    float* o_du = out + R;
    float* o_pp = out + 2 * R;
    float* o_en = out + 5 * R;
    float* o_ex = out + 6 * R;
    float* o_mk = out + 6 * R + (long long)NB * TMAX * D;

    float *xp, *xn, *h1, *h2, *h3, *h4, *h5, *h6, *wt, *nxn, *nxp;
    unsigned* red; int *dint, *cumc;
    cudaGetSymbolAddress((void**)&xp,   g_xp);
    cudaGetSymbolAddress((void**)&xn,   g_xn);
    cudaGetSymbolAddress((void**)&h1,   g_h1);
    cudaGetSymbolAddress((void**)&h2,   g_h2);
    cudaGetSymbolAddress((void**)&h3,   g_h3);
    cudaGetSymbolAddress((void**)&h4,   g_h4);
    cudaGetSymbolAddress((void**)&h5,   g_h5);
    cudaGetSymbolAddress((void**)&h6,   g_h6);
    cudaGetSymbolAddress((void**)&wt,   g_wt);
    cudaGetSymbolAddress((void**)&nxn,  g_nxn);
    cudaGetSymbolAddress((void**)&nxp,  g_nxp);
    cudaGetSymbolAddress((void**)&red,  g_red);
    cudaGetSymbolAddress((void**)&dint, g_dint);
    cudaGetSymbolAddress((void**)&cumc, g_cumc);

    cudaFuncSetAttribute(conv_mma, cudaFuncAttributeMaxDynamicSharedMemorySize, CM_SMEM);

    const int WSL = KKC * F;

    // ---- main: init, then legal fork for side stream ----
    init_red<<<1, 32>>>(red);
    cudaEventRecord(g_ss.ev0, 0);
    cudaStreamWaitEvent(g_ss.s1, g_ss.ev0, 0);

    // ---- side (LOW priority): weight transpose (overlaps gemm_np) ----
    transpose_all<<<dim3((KKC * F + 255) / 256, 6), 256, 0, g_ss.s1>>>(
        dp_w1, dp_w2, pp_w1, pp_w2, ep_w1, ep_w2, wt);
    cudaEventRecord(g_ss.evW, g_ss.s1);

    // ---- main: note projection ----
    gemm_np<<<dim3(R / 128, 2), 256>>>(nph, np_w, np_b, x, xp);
    cudaEventRecord(g_ss.evF, 0);

    // ---- side (LOW priority): tensor branch (needs xp + wt) ----
    cudaStreamWaitEvent(g_ss.s1, g_ss.evF, 0);
    dim3 gm(R / 128, 2, 2);
    conv_mma<<<gm, 128, CM_SMEM, g_ss.s1>>>(
        xp, wt + 2 * WSL, pp_b1, h1,
        xp, wt + 4 * WSL, ep_b1, h3);
    conv_mma<<<gm, 128, CM_SMEM, g_ss.s1>>>(
        h1, wt + 3 * WSL, pp_b2, h2,
        h3, wt + 5 * WSL, ep_b2, h4);

    // ---- main: layernorm (overlaps conv_mma layer 1) ----
    ln_norm_k<<<R / 8, 256>>>(xp, ln_g, ln_b, xn, nxn, nxp, red);
    cudaEventRecord(g_ss.evL, 0);

    // side finals need red/nxp from ln_norm
    cudaStreamWaitEvent(g_ss.s1, g_ss.evL, 0);
    pp_final<<<R / 8, 256, 0, g_ss.s1>>>(h2, pp_wl, pp_bl, nxp, red, o_pp);
    ep_final<<<R / 8, 256, 0, g_ss.s1>>>(h4, ep_wl, ep_bl, o_en);
    cudaEventRecord(g_ss.evJ, g_ss.s1);

    // ---- main: duration path (fp32, exact); needs wt slots 0,1 ----
    cudaStreamWaitEvent(0, g_ss.evW, 0);
    dim3 gg(R / 128, 2);
    conv_gemm<<<gg, 256>>>(xn, wt + 0 * WSL, dp_b1, h5);
    conv_gemm<<<gg, 256>>>(h5, wt + 1 * WSL, dp_b2, h6);
    dp_final<<<R / 8, 256>>>(h6, dp_wl, dp_bl, nxn, red, o_ld, o_du, dint);
    cumsum_k<<<NB, 1024>>>(dint, cumc);
    expand_k<<<dim3(TMAX / 128, NB), 256>>>(xp, cumc, o_ex, o_mk);

    // ---- join ----
    cudaStreamWaitEvent(0, g_ss.evJ, 0);
}